// round 2
// baseline (speedup 1.0000x reference)
#include <cuda_runtime.h>
#include <math.h>

#define B_ 8
#define N_ 1024
#define D_ 512
#define H_ 4

#define TM 64
#define TN 64
#define TK 16

__device__ __align__(16) float g_Y[(size_t)B_ * H_ * N_ * D_];   // [B,H,N,D] 64 MB
__device__ __align__(16) float g_S[(size_t)B_ * H_ * N_ * N_];   // [B,H,N,N] 128 MB

// ---------------------------------------------------------------------------
// K1: Y[b,h] = x[b] @ W[h]        (M=N_, Ncols=D_, K=D_)  NN
// ---------------------------------------------------------------------------
__global__ __launch_bounds__(256) void k1_xw(const float* __restrict__ x,
                                             const float* __restrict__ W) {
    __shared__ float As[TK][TM];
    __shared__ float Bs[TK][TN];
    const int bh = blockIdx.z;
    const int b = bh >> 2, h = bh & 3;
    const float* A  = x + (size_t)b * N_ * D_;   // [N_, D_]
    const float* Bm = W + (size_t)h * D_ * D_;   // [D_, D_]
    float* C = g_Y + (size_t)bh * N_ * D_;

    const int m0 = blockIdx.y * TM;
    const int n0 = blockIdx.x * TN;
    const int tid = threadIdx.x;
    const int tx = tid & 15, ty = tid >> 4;

    const int ar = tid >> 2, ac = (tid & 3) * 4;   // A: 64 rows x 16 k, float4 on k
    const int bk = tid >> 4, bn = (tid & 15) * 4;  // B: 16 k-rows x 64 cols, float4 on cols

    float acc[4][4] = {};
    for (int k0 = 0; k0 < D_; k0 += TK) {
        float4 av = *(const float4*)&A[(size_t)(m0 + ar) * D_ + k0 + ac];
        float4 bv = *(const float4*)&Bm[(size_t)(k0 + bk) * D_ + n0 + bn];
        As[ac + 0][ar] = av.x; As[ac + 1][ar] = av.y;
        As[ac + 2][ar] = av.z; As[ac + 3][ar] = av.w;
        *(float4*)&Bs[bk][bn] = bv;
        __syncthreads();
#pragma unroll
        for (int kk = 0; kk < TK; kk++) {
            float4 a = *(const float4*)&As[kk][ty * 4];
            float4 bb = *(const float4*)&Bs[kk][tx * 4];
            float ai[4] = {a.x, a.y, a.z, a.w};
            float bj[4] = {bb.x, bb.y, bb.z, bb.w};
#pragma unroll
            for (int i = 0; i < 4; i++)
#pragma unroll
                for (int j = 0; j < 4; j++) acc[i][j] += ai[i] * bj[j];
        }
        __syncthreads();
    }
#pragma unroll
    for (int i = 0; i < 4; i++) {
        float4 v = make_float4(acc[i][0], acc[i][1], acc[i][2], acc[i][3]);
        *(float4*)&C[(size_t)(m0 + ty * 4 + i) * D_ + n0 + tx * 4] = v;
    }
}

// ---------------------------------------------------------------------------
// K2: S[b,h] = scale * Y[b,h] @ x[b]^T   (M=N_, Ncols=N_, K=D_)  NT
// ---------------------------------------------------------------------------
__global__ __launch_bounds__(256) void k2_s(const float* __restrict__ x) {
    __shared__ float As[TK][TM];
    __shared__ float Bs[TK][TN];
    const int bh = blockIdx.z;
    const int b = bh >> 2;
    const float* A  = g_Y + (size_t)bh * N_ * D_;  // [N_, D_]
    const float* Bm = x + (size_t)b * N_ * D_;     // [N_, D_] rows are the "m" dim
    float* C = g_S + (size_t)bh * N_ * N_;
    const float SCALE = 0.04419417382415922f;      // 512^-0.5

    const int m0 = blockIdx.y * TM;   // n rows
    const int n0 = blockIdx.x * TN;   // m cols
    const int tid = threadIdx.x;
    const int tx = tid & 15, ty = tid >> 4;

    const int ar = tid >> 2, ac = (tid & 3) * 4;   // both operands: 64 rows x 16 k

    float acc[4][4] = {};
    for (int k0 = 0; k0 < D_; k0 += TK) {
        float4 av = *(const float4*)&A[(size_t)(m0 + ar) * D_ + k0 + ac];
        float4 bv = *(const float4*)&Bm[(size_t)(n0 + ar) * D_ + k0 + ac];
        As[ac + 0][ar] = av.x; As[ac + 1][ar] = av.y;
        As[ac + 2][ar] = av.z; As[ac + 3][ar] = av.w;
        Bs[ac + 0][ar] = bv.x; Bs[ac + 1][ar] = bv.y;
        Bs[ac + 2][ar] = bv.z; Bs[ac + 3][ar] = bv.w;
        __syncthreads();
#pragma unroll
        for (int kk = 0; kk < TK; kk++) {
            float4 a = *(const float4*)&As[kk][ty * 4];
            float4 bb = *(const float4*)&Bs[kk][tx * 4];
            float ai[4] = {a.x, a.y, a.z, a.w};
            float bj[4] = {bb.x, bb.y, bb.z, bb.w};
#pragma unroll
            for (int i = 0; i < 4; i++)
#pragma unroll
                for (int j = 0; j < 4; j++) acc[i][j] += ai[i] * bj[j];
        }
        __syncthreads();
    }
#pragma unroll
    for (int i = 0; i < 4; i++) {
        float4 v = make_float4(acc[i][0] * SCALE, acc[i][1] * SCALE,
                               acc[i][2] * SCALE, acc[i][3] * SCALE);
        *(float4*)&C[(size_t)(m0 + ty * 4 + i) * N_ + n0 + tx * 4] = v;
    }
}

// ---------------------------------------------------------------------------
// K3: row softmax over last dim of g_S. One block per row (B*H*N rows of 1024).
// ---------------------------------------------------------------------------
__global__ __launch_bounds__(256) void k3_softmax() {
    const size_t row = blockIdx.x;
    float* p = g_S + row * N_;
    const int tid = threadIdx.x;
    __shared__ float red[8];

    float4 v = *(const float4*)&p[tid * 4];
    float m = fmaxf(fmaxf(v.x, v.y), fmaxf(v.z, v.w));
#pragma unroll
    for (int o = 16; o; o >>= 1) m = fmaxf(m, __shfl_xor_sync(0xFFFFFFFFu, m, o));
    if ((tid & 31) == 0) red[tid >> 5] = m;
    __syncthreads();
    float bm = red[0];
#pragma unroll
    for (int i = 1; i < 8; i++) bm = fmaxf(bm, red[i]);
    __syncthreads();

    v.x = __expf(v.x - bm); v.y = __expf(v.y - bm);
    v.z = __expf(v.z - bm); v.w = __expf(v.w - bm);
    float s = v.x + v.y + v.z + v.w;
#pragma unroll
    for (int o = 16; o; o >>= 1) s += __shfl_xor_sync(0xFFFFFFFFu, s, o);
    if ((tid & 31) == 0) red[tid >> 5] = s;
    __syncthreads();
    float bs = 0.f;
#pragma unroll
    for (int i = 0; i < 8; i++) bs += red[i];
    float inv = 1.0f / bs;

    v.x *= inv; v.y *= inv; v.z *= inv; v.w *= inv;
    *(float4*)&p[tid * 4] = v;
}

// ---------------------------------------------------------------------------
// K4: out[b] = 0.25 * sum_h P[b,h] @ x[b]   (M=N_, Ncols=D_, K=N_ per head) NN
// ---------------------------------------------------------------------------
__global__ __launch_bounds__(256) void k4_out(const float* __restrict__ x,
                                              float* __restrict__ out) {
    __shared__ float As[TK][TM];
    __shared__ float Bs[TK][TN];
    const int b = blockIdx.z;
    const float* Bm = x + (size_t)b * N_ * D_;    // [N_, D_]
    float* C = out + (size_t)b * N_ * D_;

    const int m0 = blockIdx.y * TM;
    const int n0 = blockIdx.x * TN;
    const int tid = threadIdx.x;
    const int tx = tid & 15, ty = tid >> 4;

    const int ar = tid >> 2, ac = (tid & 3) * 4;
    const int bk = tid >> 4, bn = (tid & 15) * 4;

    float acc[4][4] = {};
    for (int h = 0; h < H_; h++) {
        const float* A = g_S + (size_t)(b * H_ + h) * N_ * N_;  // [N_, N_]
        for (int k0 = 0; k0 < N_; k0 += TK) {
            float4 av = *(const float4*)&A[(size_t)(m0 + ar) * N_ + k0 + ac];
            float4 bv = *(const float4*)&Bm[(size_t)(k0 + bk) * D_ + n0 + bn];
            As[ac + 0][ar] = av.x; As[ac + 1][ar] = av.y;
            As[ac + 2][ar] = av.z; As[ac + 3][ar] = av.w;
            *(float4*)&Bs[bk][bn] = bv;
            __syncthreads();
#pragma unroll
            for (int kk = 0; kk < TK; kk++) {
                float4 a = *(const float4*)&As[kk][ty * 4];
                float4 bb = *(const float4*)&Bs[kk][tx * 4];
                float ai[4] = {a.x, a.y, a.z, a.w};
                float bj[4] = {bb.x, bb.y, bb.z, bb.w};
#pragma unroll
                for (int i = 0; i < 4; i++)
#pragma unroll
                    for (int j = 0; j < 4; j++) acc[i][j] += ai[i] * bj[j];
            }
            __syncthreads();
        }
    }
#pragma unroll
    for (int i = 0; i < 4; i++) {
        float4 v = make_float4(acc[i][0] * 0.25f, acc[i][1] * 0.25f,
                               acc[i][2] * 0.25f, acc[i][3] * 0.25f);
        *(float4*)&C[(size_t)(m0 + ty * 4 + i) * D_ + n0 + tx * 4] = v;
    }
}

// ---------------------------------------------------------------------------
extern "C" void kernel_launch(void* const* d_in, const int* in_sizes, int n_in,
                              void* d_out, int out_size) {
    const float* x = (const float*)d_in[0];   // [8,1024,512]
    const float* W = (const float*)d_in[1];   // [4,512,512]
    float* out = (float*)d_out;               // [8,1024,512]

    dim3 blk(256);
    k1_xw<<<dim3(D_ / TN, N_ / TM, B_ * H_), blk>>>(x, W);
    k2_s<<<dim3(N_ / TN, N_ / TM, B_ * H_), blk>>>(x);
    k3_softmax<<<B_ * H_ * N_, 256>>>();
    k4_out<<<dim3(D_ / TN, N_ / TM, B_), blk>>>(x, out);
}

// round 4
// speedup vs baseline: 2.3917x; 2.3917x over previous
#include <cuda_runtime.h>
#include <cuda_bf16.h>
#include <cstdint>
#include <math.h>

#define B_ 8
#define N_ 1024
#define D_ 512
#define H_ 4

// ---------------------------------------------------------------------------
// Scratch (device globals; no allocation allowed)
// ---------------------------------------------------------------------------
__device__ __align__(16) __nv_bfloat16 g_xs_hi[(size_t)B_ * N_ * D_];
__device__ __align__(16) __nv_bfloat16 g_xs_lo[(size_t)B_ * N_ * D_];
__device__ __align__(16) __nv_bfloat16 g_xt_hi[(size_t)B_ * D_ * N_];
__device__ __align__(16) __nv_bfloat16 g_xt_lo[(size_t)B_ * D_ * N_];
__device__ __align__(16) __nv_bfloat16 g_Wt_hi[(size_t)H_ * D_ * D_];
__device__ __align__(16) __nv_bfloat16 g_Wt_lo[(size_t)H_ * D_ * D_];
__device__ __align__(16) __nv_bfloat16 g_Y_hi[(size_t)B_ * H_ * N_ * D_];
__device__ __align__(16) __nv_bfloat16 g_Y_lo[(size_t)B_ * H_ * N_ * D_];
__device__ __align__(16) float         g_S  [(size_t)B_ * H_ * N_ * N_];
__device__ __align__(16) __nv_bfloat16 g_P_hi[(size_t)B_ * H_ * N_ * N_];
__device__ __align__(16) __nv_bfloat16 g_P_lo[(size_t)B_ * H_ * N_ * N_];

// ---------------------------------------------------------------------------
// helpers (all portable sm_80+ PTX: cp.async, ldmatrix, mma.sync bf16)
// ---------------------------------------------------------------------------
__device__ __forceinline__ uint32_t smem_u32(const void* p) {
    uint32_t a;
    asm("{ .reg .u64 t; cvta.to.shared.u64 t, %1; cvt.u32.u64 %0, t; }"
        : "=r"(a) : "l"(p));
    return a;
}

#define CP16(dst, src) \
    asm volatile("cp.async.cg.shared.global [%0], [%1], 16;" \
                 :: "r"(dst), "l"(src))
#define CP_COMMIT() asm volatile("cp.async.commit_group;" ::: "memory")
#define CP_WAIT1()  asm volatile("cp.async.wait_group 1;"  ::: "memory")
#define CP_WAIT0()  asm volatile("cp.async.wait_group 0;"  ::: "memory")

#define LDSM4(r, a)                                                           \
    asm volatile("ldmatrix.sync.aligned.m8n8.x4.shared.b16 {%0,%1,%2,%3}, [%4];" \
                 : "=r"((r)[0]), "=r"((r)[1]), "=r"((r)[2]), "=r"((r)[3])     \
                 : "r"(a))
#define LDSM2(r, a)                                                           \
    asm volatile("ldmatrix.sync.aligned.m8n8.x2.shared.b16 {%0,%1}, [%2];"    \
                 : "=r"((r)[0]), "=r"((r)[1]) : "r"(a))

#define MMA(c, a, b)                                                          \
    asm volatile("mma.sync.aligned.m16n8k16.row.col.f32.bf16.bf16.f32 "       \
                 "{%0,%1,%2,%3},{%4,%5,%6,%7},{%8,%9},{%0,%1,%2,%3};"         \
                 : "+f"((c)[0]), "+f"((c)[1]), "+f"((c)[2]), "+f"((c)[3])     \
                 : "r"((a)[0]), "r"((a)[1]), "r"((a)[2]), "r"((a)[3]),        \
                   "r"((b)[0]), "r"((b)[1]))

// smem tile geometry: 128 rows x 32 bf16 (64B data), pitch 80B for
// conflict-free ldmatrix (bank stride 20 -> 8 consecutive rows distinct)
#define PITCH_B 80
#define TILE_B  (128 * PITCH_B)       // 10240
#define BUF_B   (4 * TILE_B)          // 40960: AH, AL, BH, BL
#define GSMEM   (2 * BUF_B)           // 81920 double-buffered

// ---------------------------------------------------------------------------
// Generic split-bf16 mma.sync GEMM (NT):
//   C[m,n] = alpha * sum_seg sum_k (Ahi+Alo)[m,k] * (Bhi+Blo)[n,k]
// CTA tile 128x128, 8 warps (2m x 4n), warp tile 64x32, K-chunk 32.
// EPI 0: fp32 C.  EPI 1: (hi,lo) bf16 pair.
// ---------------------------------------------------------------------------
template <int EPI>
__global__ __launch_bounds__(256, 1) void gemm_mma(
    const __nv_bfloat16* __restrict__ Ahi, const __nv_bfloat16* __restrict__ Alo,
    int ldA, size_t aBatch, int aDiv, int aMod, size_t aSeg,
    const __nv_bfloat16* __restrict__ Bhi, const __nv_bfloat16* __restrict__ Blo,
    int ldB, size_t bBatch, int bDiv, int bMod,
    int Kseg, int nSeg,
    float* __restrict__ Cf,
    __nv_bfloat16* __restrict__ Chi, __nv_bfloat16* __restrict__ Clo,
    int ldC, size_t cBatch, float alpha)
{
    extern __shared__ char smem[];
    const uint32_t sb = smem_u32(smem);
    const int tid = threadIdx.x;
    const int wid = tid >> 5, lane = tid & 31;
    const int wm = (wid >> 2) * 64;     // warp m-offset in CTA tile
    const int wn = (wid & 3) * 32;      // warp n-offset
    const int z = blockIdx.z;
    const int m0 = blockIdx.y * 128;
    const int n0 = blockIdx.x * 128;

    const size_t aOff = (size_t)((z / aDiv) % aMod) * aBatch;
    const size_t bOff = (size_t)((z / bDiv) % bMod) * bBatch;
    Ahi += aOff; Alo += aOff; Bhi += bOff; Blo += bOff;

    const int cps = Kseg / 32;          // chunks per segment
    const int total = nSeg * cps;

    // per-thread load slots: idx in [0,512): row = idx>>2, 16B piece = idx&3
    const int lrow = (tid * 2) >> 2;          // rows for it=0 (idx=tid*2)
    // use idx = tid + it*256 instead (simpler):
#define LOAD_CHUNK(ch) do {                                                   \
        const int seg_ = (ch) / cps;                                          \
        const int k0_ = ((ch) % cps) * 32;                                    \
        const uint32_t bb_ = sb + ((ch) & 1) * BUF_B;                         \
        const __nv_bfloat16* Ah_ = Ahi + (size_t)seg_ * aSeg;                 \
        const __nv_bfloat16* Al_ = Alo + (size_t)seg_ * aSeg;                 \
        _Pragma("unroll")                                                     \
        for (int it = 0; it < 2; it++) {                                      \
            const int idx = tid + it * 256;                                   \
            const int row = idx >> 2;                                         \
            const int c4 = idx & 3;                                           \
            const uint32_t d = row * PITCH_B + c4 * 16;                       \
            const size_t ga = (size_t)(m0 + row) * ldA + k0_ + c4 * 8;        \
            const size_t gb = (size_t)(n0 + row) * ldB + k0_ + c4 * 8;        \
            CP16(bb_ + 0 * TILE_B + d, (const char*)(Ah_ + ga));              \
            CP16(bb_ + 1 * TILE_B + d, (const char*)(Al_ + ga));              \
            CP16(bb_ + 2 * TILE_B + d, (const char*)(Bhi + gb));              \
            CP16(bb_ + 3 * TILE_B + d, (const char*)(Blo + gb));              \
        }                                                                     \
    } while (0)

    float acc[4][4][4];
#pragma unroll
    for (int i = 0; i < 4; i++)
#pragma unroll
        for (int j = 0; j < 4; j++)
#pragma unroll
            for (int r = 0; r < 4; r++) acc[i][j][r] = 0.f;

    LOAD_CHUNK(0);
    CP_COMMIT();

    for (int ch = 0; ch < total; ch++) {
        if (ch + 1 < total) {
            LOAD_CHUNK(ch + 1);
            CP_COMMIT();
            CP_WAIT1();
        } else {
            CP_WAIT0();
        }
        __syncthreads();

        const uint32_t bb = sb + (ch & 1) * BUF_B;
        const uint32_t sAH = bb, sAL = bb + TILE_B;
        const uint32_t sBH = bb + 2 * TILE_B, sBL = bb + 3 * TILE_B;

        const int aRow = lane & 15;
        const int aColB0 = (lane & 16);        // ((lane&16)>>1) elems * 2B
        const int bRow = lane & 7;
        const int bColB0 = ((lane >> 3) & 1) * 16;

#pragma unroll
        for (int ks = 0; ks < 2; ks++) {
            uint32_t ah[4][4], al[4][4], bh[4][2], bl[4][2];
            const int aColB = ks * 32 + aColB0;
            const int bColB = ks * 32 + bColB0;
#pragma unroll
            for (int i = 0; i < 4; i++) {
                const uint32_t ra = (wm + i * 16 + aRow) * PITCH_B + aColB;
                LDSM4(ah[i], sAH + ra);
                LDSM4(al[i], sAL + ra);
            }
#pragma unroll
            for (int j = 0; j < 4; j++) {
                const uint32_t rb = (wn + j * 8 + bRow) * PITCH_B + bColB;
                LDSM2(bh[j], sBH + rb);
                LDSM2(bl[j], sBL + rb);
            }
#pragma unroll
            for (int i = 0; i < 4; i++)
#pragma unroll
                for (int j = 0; j < 4; j++) {
                    MMA(acc[i][j], ah[i], bh[j]);
                    MMA(acc[i][j], ah[i], bl[j]);
                    MMA(acc[i][j], al[i], bh[j]);
                }
        }
        __syncthreads();
    }
#undef LOAD_CHUNK

    // ---- epilogue ----
    const int cr = lane >> 2, cc = (lane & 3) * 2;
#pragma unroll
    for (int i = 0; i < 4; i++) {
        const int r0 = m0 + wm + i * 16 + cr;
#pragma unroll
        for (int j = 0; j < 4; j++) {
            const int col = n0 + wn + j * 8 + cc;
            const size_t o0 = (size_t)z * cBatch + (size_t)r0 * ldC + col;
            const size_t o1 = o0 + (size_t)8 * ldC;
            float v0 = acc[i][j][0] * alpha, v1 = acc[i][j][1] * alpha;
            float v2 = acc[i][j][2] * alpha, v3 = acc[i][j][3] * alpha;
            if (EPI == 0) {
                Cf[o0] = v0; Cf[o0 + 1] = v1;
                Cf[o1] = v2; Cf[o1 + 1] = v3;
            } else {
                __nv_bfloat16 h0 = __float2bfloat16(v0);
                __nv_bfloat16 h1 = __float2bfloat16(v1);
                __nv_bfloat16 h2 = __float2bfloat16(v2);
                __nv_bfloat16 h3 = __float2bfloat16(v3);
                Chi[o0] = h0; Chi[o0 + 1] = h1;
                Chi[o1] = h2; Chi[o1 + 1] = h3;
                Clo[o0] = __float2bfloat16(v0 - __bfloat162float(h0));
                Clo[o0 + 1] = __float2bfloat16(v1 - __bfloat162float(h1));
                Clo[o1] = __float2bfloat16(v2 - __bfloat162float(h2));
                Clo[o1 + 1] = __float2bfloat16(v3 - __bfloat162float(h3));
            }
        }
    }
    (void)lrow;
}

// ---------------------------------------------------------------------------
// Split x -> xs (hi/lo, [B,N,D]) and xt (hi/lo, [B,D,N])
// ---------------------------------------------------------------------------
__global__ __launch_bounds__(256) void split_x_kernel(const float* __restrict__ x) {
    __shared__ float t[32][33];
    const int b = blockIdx.z;
    const int d0 = blockIdx.x * 32, n0 = blockIdx.y * 32;
    const int tx = threadIdx.x & 31, ty = threadIdx.x >> 5;

    for (int i = ty; i < 32; i += 8)
        t[i][tx] = x[(size_t)b * N_ * D_ + (size_t)(n0 + i) * D_ + d0 + tx];
    __syncthreads();

    for (int i = ty; i < 32; i += 8) {
        float v = t[i][tx];
        __nv_bfloat16 hi = __float2bfloat16(v);
        __nv_bfloat16 lo = __float2bfloat16(v - __bfloat162float(hi));
        size_t o = (size_t)b * N_ * D_ + (size_t)(n0 + i) * D_ + d0 + tx;
        g_xs_hi[o] = hi; g_xs_lo[o] = lo;
    }
    for (int i = ty; i < 32; i += 8) {
        float v = t[tx][i];
        __nv_bfloat16 hi = __float2bfloat16(v);
        __nv_bfloat16 lo = __float2bfloat16(v - __bfloat162float(hi));
        size_t o = (size_t)b * D_ * N_ + (size_t)(d0 + i) * N_ + n0 + tx;
        g_xt_hi[o] = hi; g_xt_lo[o] = lo;
    }
}

__global__ __launch_bounds__(256) void split_w_kernel(const float* __restrict__ W) {
    __shared__ float t[32][33];
    const int h = blockIdx.z;
    const int e0 = blockIdx.x * 32, d0 = blockIdx.y * 32;
    const int tx = threadIdx.x & 31, ty = threadIdx.x >> 5;

    for (int i = ty; i < 32; i += 8)
        t[i][tx] = W[(size_t)h * D_ * D_ + (size_t)(d0 + i) * D_ + e0 + tx];
    __syncthreads();

    for (int i = ty; i < 32; i += 8) {
        float v = t[tx][i];   // W[d0+tx][e0+i]
        __nv_bfloat16 hi = __float2bfloat16(v);
        __nv_bfloat16 lo = __float2bfloat16(v - __bfloat162float(hi));
        size_t o = (size_t)h * D_ * D_ + (size_t)(e0 + i) * D_ + d0 + tx;
        g_Wt_hi[o] = hi; g_Wt_lo[o] = lo;
    }
}

// ---------------------------------------------------------------------------
// Softmax over rows of g_S; writes hi/lo bf16 P
// ---------------------------------------------------------------------------
__global__ __launch_bounds__(256) void softmax_split_kernel() {
    const size_t row = blockIdx.x;
    const float* p = g_S + row * N_;
    const int tid = threadIdx.x;
    __shared__ float red[8];

    float4 v = *(const float4*)&p[tid * 4];
    float m = fmaxf(fmaxf(v.x, v.y), fmaxf(v.z, v.w));
#pragma unroll
    for (int o = 16; o; o >>= 1) m = fmaxf(m, __shfl_xor_sync(0xFFFFFFFFu, m, o));
    if ((tid & 31) == 0) red[tid >> 5] = m;
    __syncthreads();
    float bm = red[0];
#pragma unroll
    for (int i = 1; i < 8; i++) bm = fmaxf(bm, red[i]);
    __syncthreads();

    v.x = __expf(v.x - bm); v.y = __expf(v.y - bm);
    v.z = __expf(v.z - bm); v.w = __expf(v.w - bm);
    float s = v.x + v.y + v.z + v.w;
#pragma unroll
    for (int o = 16; o; o >>= 1) s += __shfl_xor_sync(0xFFFFFFFFu, s, o);
    if ((tid & 31) == 0) red[tid >> 5] = s;
    __syncthreads();
    float bs = 0.f;
#pragma unroll
    for (int i = 0; i < 8; i++) bs += red[i];
    float inv = 1.0f / bs;

    float vals[4] = {v.x * inv, v.y * inv, v.z * inv, v.w * inv};
#pragma unroll
    for (int j = 0; j < 4; j++) {
        __nv_bfloat16 hi = __float2bfloat16(vals[j]);
        __nv_bfloat16 lo = __float2bfloat16(vals[j] - __bfloat162float(hi));
        g_P_hi[row * N_ + tid * 4 + j] = hi;
        g_P_lo[row * N_ + tid * 4 + j] = lo;
    }
}

// ---------------------------------------------------------------------------
extern "C" void kernel_launch(void* const* d_in, const int* in_sizes, int n_in,
                              void* d_out, int out_size) {
    const float* x = (const float*)d_in[0];   // [8,1024,512]
    const float* W = (const float*)d_in[1];   // [4,512,512]
    float* out = (float*)d_out;               // [8,1024,512]

    cudaFuncSetAttribute(gemm_mma<0>, cudaFuncAttributeMaxDynamicSharedMemorySize, GSMEM);
    cudaFuncSetAttribute(gemm_mma<1>, cudaFuncAttributeMaxDynamicSharedMemorySize, GSMEM);

    __nv_bfloat16 *xs_hi, *xs_lo, *xt_hi, *xt_lo, *Wt_hi, *Wt_lo;
    __nv_bfloat16 *Y_hi, *Y_lo, *P_hi, *P_lo;
    float* Sf;
    cudaGetSymbolAddress((void**)&xs_hi, g_xs_hi);
    cudaGetSymbolAddress((void**)&xs_lo, g_xs_lo);
    cudaGetSymbolAddress((void**)&xt_hi, g_xt_hi);
    cudaGetSymbolAddress((void**)&xt_lo, g_xt_lo);
    cudaGetSymbolAddress((void**)&Wt_hi, g_Wt_hi);
    cudaGetSymbolAddress((void**)&Wt_lo, g_Wt_lo);
    cudaGetSymbolAddress((void**)&Y_hi, g_Y_hi);
    cudaGetSymbolAddress((void**)&Y_lo, g_Y_lo);
    cudaGetSymbolAddress((void**)&P_hi, g_P_hi);
    cudaGetSymbolAddress((void**)&P_lo, g_P_lo);
    cudaGetSymbolAddress((void**)&Sf, g_S);

    const float SCALE = 0.04419417382415922f;   // 512^-0.5

    split_x_kernel<<<dim3(D_ / 32, N_ / 32, B_), 256>>>(x);
    split_w_kernel<<<dim3(D_ / 32, D_ / 32, H_), 256>>>(W);

    // K1: Y[b,h] = xs[b] @ Wt[h]^T  -> split bf16 Y
    gemm_mma<1><<<dim3(D_ / 128, N_ / 128, B_ * H_), 256, GSMEM>>>(
        xs_hi, xs_lo, D_, (size_t)N_ * D_, 4, 8, 0,
        Wt_hi, Wt_lo, D_, (size_t)D_ * D_, 1, 4,
        D_, 1,
        nullptr, Y_hi, Y_lo, D_, (size_t)N_ * D_, 1.0f);

    // K2: S[b,h] = scale * Y[b,h] @ xs[b]^T  -> fp32
    gemm_mma<0><<<dim3(N_ / 128, N_ / 128, B_ * H_), 256, GSMEM>>>(
        Y_hi, Y_lo, D_, (size_t)N_ * D_, 1, 32, 0,
        xs_hi, xs_lo, D_, (size_t)N_ * D_, 4, 8,
        D_, 1,
        Sf, nullptr, nullptr, N_, (size_t)N_ * N_, SCALE);

    softmax_split_kernel<<<B_ * H_ * N_, 256>>>();

    // K4: out[b] = 0.25 * sum_h P[b,h] @ xt[b]^T  -> fp32
    gemm_mma<0><<<dim3(D_ / 128, N_ / 128, B_), 256, GSMEM>>>(
        P_hi, P_lo, N_, (size_t)H_ * N_ * N_, 1, 8, (size_t)N_ * N_,
        xt_hi, xt_lo, N_, (size_t)D_ * N_, 1, 8,
        N_, H_,
        out, nullptr, nullptr, D_, (size_t)N_ * D_, 0.25f);
}

// round 5
// speedup vs baseline: 3.1313x; 1.3092x over previous
#include <cuda_runtime.h>
#include <cuda_bf16.h>
#include <cstdint>
#include <math.h>

#define B_ 8
#define N_ 1024
#define D_ 512
#define H_ 4

// ---------------------------------------------------------------------------
// Scratch (device globals; no allocation allowed)
// ---------------------------------------------------------------------------
__device__ __align__(16) __nv_bfloat16 g_xs_hi[(size_t)B_ * N_ * D_];
__device__ __align__(16) __nv_bfloat16 g_xs_lo[(size_t)B_ * N_ * D_];
__device__ __align__(16) __nv_bfloat16 g_xt_hi[(size_t)B_ * D_ * N_];
__device__ __align__(16) __nv_bfloat16 g_xt_lo[(size_t)B_ * D_ * N_];
__device__ __align__(16) __nv_bfloat16 g_Wt_hi[(size_t)H_ * D_ * D_];
__device__ __align__(16) __nv_bfloat16 g_Wt_lo[(size_t)H_ * D_ * D_];
__device__ __align__(16) __nv_bfloat16 g_Y_hi[(size_t)B_ * H_ * N_ * D_];
__device__ __align__(16) __nv_bfloat16 g_Y_lo[(size_t)B_ * H_ * N_ * D_];
__device__ __align__(16) float         g_S  [(size_t)B_ * H_ * N_ * N_];
__device__ __align__(16) __nv_bfloat16 g_P_hi[(size_t)B_ * H_ * N_ * N_];
__device__ __align__(16) __nv_bfloat16 g_P_lo[(size_t)B_ * H_ * N_ * N_];

// ---------------------------------------------------------------------------
// helpers (portable sm_80+ PTX)
// ---------------------------------------------------------------------------
__device__ __forceinline__ uint32_t smem_u32(const void* p) {
    uint32_t a;
    asm("{ .reg .u64 t; cvta.to.shared.u64 t, %1; cvt.u32.u64 %0, t; }"
        : "=r"(a) : "l"(p));
    return a;
}

#define CP16(dst, src) \
    asm volatile("cp.async.cg.shared.global [%0], [%1], 16;" \
                 :: "r"(dst), "l"(src))
#define CP_COMMIT() asm volatile("cp.async.commit_group;" ::: "memory")
#define CP_WAIT1()  asm volatile("cp.async.wait_group 1;"  ::: "memory")
#define CP_WAIT0()  asm volatile("cp.async.wait_group 0;"  ::: "memory")

#define LDSM4(r, a)                                                           \
    asm volatile("ldmatrix.sync.aligned.m8n8.x4.shared.b16 {%0,%1,%2,%3}, [%4];" \
                 : "=r"((r)[0]), "=r"((r)[1]), "=r"((r)[2]), "=r"((r)[3])     \
                 : "r"(a))
#define LDSM2(r, a)                                                           \
    asm volatile("ldmatrix.sync.aligned.m8n8.x2.shared.b16 {%0,%1}, [%2];"    \
                 : "=r"((r)[0]), "=r"((r)[1]) : "r"(a))

#define MMA(c, a, b)                                                          \
    asm volatile("mma.sync.aligned.m16n8k16.row.col.f32.bf16.bf16.f32 "       \
                 "{%0,%1,%2,%3},{%4,%5,%6,%7},{%8,%9},{%0,%1,%2,%3};"         \
                 : "+f"((c)[0]), "+f"((c)[1]), "+f"((c)[2]), "+f"((c)[3])     \
                 : "r"((a)[0]), "r"((a)[1]), "r"((a)[2]), "r"((a)[3]),        \
                   "r"((b)[0]), "r"((b)[1]))

// SW128-style swizzle within a 128B row: col ^= (row & 7) * 16
#define SWZC(row, colB) ((uint32_t)(colB) ^ (((uint32_t)(row) & 7u) << 4))

// smem geometry: rows are exactly 128B (64 bf16), swizzled.
// CTA tile: A 128x64, B 64x64, K-chunk 64, double buffered.
#define AT_B   (128 * 128)               // 16384
#define BT_B   (64 * 128)                // 8192
#define STG_B  (2 * AT_B + 2 * BT_B)     // 49152: AH, AL, BH, BL
#define OFF_AH 0
#define OFF_AL AT_B
#define OFF_BH (2 * AT_B)
#define OFF_BL (2 * AT_B + BT_B)
#define GSMEM  (2 * STG_B)               // 98304

// ---------------------------------------------------------------------------
// Split-bf16 mma.sync GEMM (NT): C[m,n] = alpha * sum_seg sum_k A[m,k]B[n,k]
// CTA tile 128x64, 8 warps (4m x 2n), warp tile 32x32, K-chunk 64, 2 CTAs/SM.
// EPI 0: fp32 C.  EPI 1: (hi,lo) bf16 pair.
// ---------------------------------------------------------------------------
template <int EPI>
__global__ __launch_bounds__(256, 2) void gemm_mma(
    const __nv_bfloat16* __restrict__ Ahi, const __nv_bfloat16* __restrict__ Alo,
    int ldA, size_t aBatch, int aDiv, int aMod, size_t aSeg,
    const __nv_bfloat16* __restrict__ Bhi, const __nv_bfloat16* __restrict__ Blo,
    int ldB, size_t bBatch, int bDiv, int bMod,
    int Kseg, int nSeg,
    float* __restrict__ Cf,
    __nv_bfloat16* __restrict__ Chi, __nv_bfloat16* __restrict__ Clo,
    int ldC, size_t cBatch, float alpha)
{
    extern __shared__ char smem[];
    const uint32_t sb = smem_u32(smem);
    const int tid = threadIdx.x;
    const int wid = tid >> 5, lane = tid & 31;
    const int wm = (wid >> 1) * 32;     // warp m-offset (4 groups)
    const int wn = (wid & 1) * 32;      // warp n-offset (2 groups)
    const int z = blockIdx.z;
    const int m0 = blockIdx.y * 128;
    const int n0 = blockIdx.x * 64;

    const size_t aOff = (size_t)((z / aDiv) % aMod) * aBatch;
    const size_t bOff = (size_t)((z / bDiv) % bMod) * bBatch;
    Ahi += aOff; Alo += aOff; Bhi += bOff; Blo += bOff;

    const int cps = Kseg / 64;          // chunks per segment
    const int total = nSeg * cps;

#define LOAD_CHUNK(ch) do {                                                   \
        const int seg_ = (ch) / cps;                                          \
        const int k0_ = ((ch) % cps) * 64;                                    \
        const uint32_t bb_ = sb + ((ch) & 1) * STG_B;                         \
        const __nv_bfloat16* Ah_ = Ahi + (size_t)seg_ * aSeg;                 \
        const __nv_bfloat16* Al_ = Alo + (size_t)seg_ * aSeg;                 \
        _Pragma("unroll")                                                     \
        for (int it = 0; it < 4; it++) {     /* A: 128 rows x 8 pieces */     \
            const int idx = tid + it * 256;                                   \
            const int row = idx >> 3;                                         \
            const int pc = idx & 7;                                           \
            const uint32_t d = row * 128 + SWZC(row, pc * 16);                \
            const size_t ga = (size_t)(m0 + row) * ldA + k0_ + pc * 8;        \
            CP16(bb_ + OFF_AH + d, (const char*)(Ah_ + ga));                  \
            CP16(bb_ + OFF_AL + d, (const char*)(Al_ + ga));                  \
        }                                                                     \
        _Pragma("unroll")                                                     \
        for (int it = 0; it < 2; it++) {     /* B: 64 rows x 8 pieces */      \
            const int idx = tid + it * 256;                                   \
            const int row = idx >> 3;                                         \
            const int pc = idx & 7;                                           \
            const uint32_t d = row * 128 + SWZC(row, pc * 16);                \
            const size_t gb = (size_t)(n0 + row) * ldB + k0_ + pc * 8;        \
            CP16(bb_ + OFF_BH + d, (const char*)(Bhi + gb));                  \
            CP16(bb_ + OFF_BL + d, (const char*)(Blo + gb));                  \
        }                                                                     \
    } while (0)

    float acc[2][4][4];
#pragma unroll
    for (int i = 0; i < 2; i++)
#pragma unroll
        for (int j = 0; j < 4; j++)
#pragma unroll
            for (int r = 0; r < 4; r++) acc[i][j][r] = 0.f;

    LOAD_CHUNK(0);
    CP_COMMIT();

    const int aRow = lane & 15;
    const int aColB0 = (lane & 16);            // 0 or 16 bytes
    const int bRow = lane & 7;
    const int bColB0 = ((lane >> 3) & 1) * 16;

    for (int ch = 0; ch < total; ch++) {
        if (ch + 1 < total) {
            LOAD_CHUNK(ch + 1);
            CP_COMMIT();
            CP_WAIT1();
        } else {
            CP_WAIT0();
        }
        __syncthreads();

        const uint32_t bb = sb + (ch & 1) * STG_B;
        const uint32_t sAH = bb + OFF_AH, sAL = bb + OFF_AL;
        const uint32_t sBH = bb + OFF_BH, sBL = bb + OFF_BL;

#pragma unroll
        for (int ks = 0; ks < 4; ks++) {
            uint32_t ah[2][4], al[2][4], bh[4][2], bl[4][2];
            const int aColB = ks * 32 + aColB0;
            const int bColB = ks * 32 + bColB0;
#pragma unroll
            for (int i = 0; i < 2; i++) {
                const int row = wm + i * 16 + aRow;
                const uint32_t ra = row * 128 + SWZC(row, aColB);
                LDSM4(ah[i], sAH + ra);
                LDSM4(al[i], sAL + ra);
            }
#pragma unroll
            for (int j = 0; j < 4; j++) {
                const int row = wn + j * 8 + bRow;
                const uint32_t rb = row * 128 + SWZC(row, bColB);
                LDSM2(bh[j], sBH + rb);
                LDSM2(bl[j], sBL + rb);
            }
#pragma unroll
            for (int i = 0; i < 2; i++)
#pragma unroll
                for (int j = 0; j < 4; j++) {
                    MMA(acc[i][j], ah[i], bh[j]);
                    MMA(acc[i][j], ah[i], bl[j]);
                    MMA(acc[i][j], al[i], bh[j]);
                }
        }
        __syncthreads();
    }
#undef LOAD_CHUNK

    // ---- epilogue ----
    const int cr = lane >> 2, cc = (lane & 3) * 2;
#pragma unroll
    for (int i = 0; i < 2; i++) {
        const int r0 = m0 + wm + i * 16 + cr;
#pragma unroll
        for (int j = 0; j < 4; j++) {
            const int col = n0 + wn + j * 8 + cc;
            const size_t o0 = (size_t)z * cBatch + (size_t)r0 * ldC + col;
            const size_t o1 = o0 + (size_t)8 * ldC;
            float v0 = acc[i][j][0] * alpha, v1 = acc[i][j][1] * alpha;
            float v2 = acc[i][j][2] * alpha, v3 = acc[i][j][3] * alpha;
            if (EPI == 0) {
                Cf[o0] = v0; Cf[o0 + 1] = v1;
                Cf[o1] = v2; Cf[o1 + 1] = v3;
            } else {
                __nv_bfloat16 h0 = __float2bfloat16(v0);
                __nv_bfloat16 h1 = __float2bfloat16(v1);
                __nv_bfloat16 h2 = __float2bfloat16(v2);
                __nv_bfloat16 h3 = __float2bfloat16(v3);
                Chi[o0] = h0; Chi[o0 + 1] = h1;
                Chi[o1] = h2; Chi[o1 + 1] = h3;
                Clo[o0] = __float2bfloat16(v0 - __bfloat162float(h0));
                Clo[o0 + 1] = __float2bfloat16(v1 - __bfloat162float(h1));
                Clo[o1] = __float2bfloat16(v2 - __bfloat162float(h2));
                Clo[o1 + 1] = __float2bfloat16(v3 - __bfloat162float(h3));
            }
        }
    }
}

// ---------------------------------------------------------------------------
// Split x -> xs (hi/lo, [B,N,D]) and xt (hi/lo, [B,D,N])
// ---------------------------------------------------------------------------
__global__ __launch_bounds__(256) void split_x_kernel(const float* __restrict__ x) {
    __shared__ float t[32][33];
    const int b = blockIdx.z;
    const int d0 = blockIdx.x * 32, n0 = blockIdx.y * 32;
    const int tx = threadIdx.x & 31, ty = threadIdx.x >> 5;

    for (int i = ty; i < 32; i += 8)
        t[i][tx] = x[(size_t)b * N_ * D_ + (size_t)(n0 + i) * D_ + d0 + tx];
    __syncthreads();

    for (int i = ty; i < 32; i += 8) {
        float v = t[i][tx];
        __nv_bfloat16 hi = __float2bfloat16(v);
        __nv_bfloat16 lo = __float2bfloat16(v - __bfloat162float(hi));
        size_t o = (size_t)b * N_ * D_ + (size_t)(n0 + i) * D_ + d0 + tx;
        g_xs_hi[o] = hi; g_xs_lo[o] = lo;
    }
    for (int i = ty; i < 32; i += 8) {
        float v = t[tx][i];
        __nv_bfloat16 hi = __float2bfloat16(v);
        __nv_bfloat16 lo = __float2bfloat16(v - __bfloat162float(hi));
        size_t o = (size_t)b * D_ * N_ + (size_t)(d0 + i) * N_ + n0 + tx;
        g_xt_hi[o] = hi; g_xt_lo[o] = lo;
    }
}

__global__ __launch_bounds__(256) void split_w_kernel(const float* __restrict__ W) {
    __shared__ float t[32][33];
    const int h = blockIdx.z;
    const int e0 = blockIdx.x * 32, d0 = blockIdx.y * 32;
    const int tx = threadIdx.x & 31, ty = threadIdx.x >> 5;

    for (int i = ty; i < 32; i += 8)
        t[i][tx] = W[(size_t)h * D_ * D_ + (size_t)(d0 + i) * D_ + e0 + tx];
    __syncthreads();

    for (int i = ty; i < 32; i += 8) {
        float v = t[tx][i];   // W[d0+tx][e0+i]
        __nv_bfloat16 hi = __float2bfloat16(v);
        __nv_bfloat16 lo = __float2bfloat16(v - __bfloat162float(hi));
        size_t o = (size_t)h * D_ * D_ + (size_t)(e0 + i) * D_ + d0 + tx;
        g_Wt_hi[o] = hi; g_Wt_lo[o] = lo;
    }
}

// ---------------------------------------------------------------------------
// Softmax over rows of g_S; writes hi/lo bf16 P
// ---------------------------------------------------------------------------
__global__ __launch_bounds__(256) void softmax_split_kernel() {
    const size_t row = blockIdx.x;
    const float* p = g_S + row * N_;
    const int tid = threadIdx.x;
    __shared__ float red[8];

    float4 v = *(const float4*)&p[tid * 4];
    float m = fmaxf(fmaxf(v.x, v.y), fmaxf(v.z, v.w));
#pragma unroll
    for (int o = 16; o; o >>= 1) m = fmaxf(m, __shfl_xor_sync(0xFFFFFFFFu, m, o));
    if ((tid & 31) == 0) red[tid >> 5] = m;
    __syncthreads();
    float bm = red[0];
#pragma unroll
    for (int i = 1; i < 8; i++) bm = fmaxf(bm, red[i]);
    __syncthreads();

    v.x = __expf(v.x - bm); v.y = __expf(v.y - bm);
    v.z = __expf(v.z - bm); v.w = __expf(v.w - bm);
    float s = v.x + v.y + v.z + v.w;
#pragma unroll
    for (int o = 16; o; o >>= 1) s += __shfl_xor_sync(0xFFFFFFFFu, s, o);
    if ((tid & 31) == 0) red[tid >> 5] = s;
    __syncthreads();
    float bs = 0.f;
#pragma unroll
    for (int i = 0; i < 8; i++) bs += red[i];
    float inv = 1.0f / bs;

    float vals[4] = {v.x * inv, v.y * inv, v.z * inv, v.w * inv};
#pragma unroll
    for (int j = 0; j < 4; j++) {
        __nv_bfloat16 hi = __float2bfloat16(vals[j]);
        __nv_bfloat16 lo = __float2bfloat16(vals[j] - __bfloat162float(hi));
        g_P_hi[row * N_ + tid * 4 + j] = hi;
        g_P_lo[row * N_ + tid * 4 + j] = lo;
    }
}

// ---------------------------------------------------------------------------
extern "C" void kernel_launch(void* const* d_in, const int* in_sizes, int n_in,
                              void* d_out, int out_size) {
    const float* x = (const float*)d_in[0];   // [8,1024,512]
    const float* W = (const float*)d_in[1];   // [4,512,512]
    float* out = (float*)d_out;               // [8,1024,512]

    cudaFuncSetAttribute(gemm_mma<0>, cudaFuncAttributeMaxDynamicSharedMemorySize, GSMEM);
    cudaFuncSetAttribute(gemm_mma<1>, cudaFuncAttributeMaxDynamicSharedMemorySize, GSMEM);

    __nv_bfloat16 *xs_hi, *xs_lo, *xt_hi, *xt_lo, *Wt_hi, *Wt_lo;
    __nv_bfloat16 *Y_hi, *Y_lo, *P_hi, *P_lo;
    float* Sf;
    cudaGetSymbolAddress((void**)&xs_hi, g_xs_hi);
    cudaGetSymbolAddress((void**)&xs_lo, g_xs_lo);
    cudaGetSymbolAddress((void**)&xt_hi, g_xt_hi);
    cudaGetSymbolAddress((void**)&xt_lo, g_xt_lo);
    cudaGetSymbolAddress((void**)&Wt_hi, g_Wt_hi);
    cudaGetSymbolAddress((void**)&Wt_lo, g_Wt_lo);
    cudaGetSymbolAddress((void**)&Y_hi, g_Y_hi);
    cudaGetSymbolAddress((void**)&Y_lo, g_Y_lo);
    cudaGetSymbolAddress((void**)&P_hi, g_P_hi);
    cudaGetSymbolAddress((void**)&P_lo, g_P_lo);
    cudaGetSymbolAddress((void**)&Sf, g_S);

    const float SCALE = 0.04419417382415922f;   // 512^-0.5

    split_x_kernel<<<dim3(D_ / 32, N_ / 32, B_), 256>>>(x);
    split_w_kernel<<<dim3(D_ / 32, D_ / 32, H_), 256>>>(W);

    // K1: Y[b,h] = xs[b] @ Wt[h]^T  -> split bf16 Y
    gemm_mma<1><<<dim3(D_ / 64, N_ / 128, B_ * H_), 256, GSMEM>>>(
        xs_hi, xs_lo, D_, (size_t)N_ * D_, 4, 8, 0,
        Wt_hi, Wt_lo, D_, (size_t)D_ * D_, 1, 4,
        D_, 1,
        nullptr, Y_hi, Y_lo, D_, (size_t)N_ * D_, 1.0f);

    // K2: S[b,h] = scale * Y[b,h] @ xs[b]^T  -> fp32
    gemm_mma<0><<<dim3(N_ / 64, N_ / 128, B_ * H_), 256, GSMEM>>>(
        Y_hi, Y_lo, D_, (size_t)N_ * D_, 1, 32, 0,
        xs_hi, xs_lo, D_, (size_t)N_ * D_, 4, 8,
        D_, 1,
        Sf, nullptr, nullptr, N_, (size_t)N_ * N_, SCALE);

    softmax_split_kernel<<<B_ * H_ * N_, 256>>>();

    // K4: out[b] = 0.25 * sum_h P[b,h] @ xt[b]^T  -> fp32
    gemm_mma<0><<<dim3(D_ / 64, N_ / 128, B_), 256, GSMEM>>>(
        P_hi, P_lo, N_, (size_t)H_ * N_ * N_, 1, 8, (size_t)N_ * N_,
        xt_hi, xt_lo, N_, (size_t)D_ * N_, 1, 8,
        N_, H_,
        out, nullptr, nullptr, D_, (size_t)N_ * D_, 0.25f);
}

// round 6
// speedup vs baseline: 3.2418x; 1.0353x over previous
#include <cuda_runtime.h>
#include <cuda_fp16.h>
#include <cstdint>
#include <math.h>

#define B_ 8
#define N_ 1024
#define D_ 512
#define H_ 4

// ---------------------------------------------------------------------------
// Scratch (device globals; no allocation allowed)
// ---------------------------------------------------------------------------
__device__ __align__(16) __half g_xs_h[(size_t)B_ * N_ * D_];
__device__ __align__(16) __half g_xs_r[(size_t)B_ * N_ * D_];
__device__ __align__(16) __half g_xt_h[(size_t)B_ * D_ * N_];
__device__ __align__(16) __half g_Wt_h[(size_t)H_ * D_ * D_];
__device__ __align__(16) __half g_Wt_r[(size_t)H_ * D_ * D_];
__device__ __align__(16) __half g_Y_h[(size_t)B_ * H_ * N_ * D_];
__device__ __align__(16) __half g_Y_r[(size_t)B_ * H_ * N_ * D_];
__device__ __align__(16) float  g_S  [(size_t)B_ * H_ * N_ * N_];  // also K4 scratch
__device__ __align__(16) __half g_P_h[(size_t)B_ * H_ * N_ * N_];
__device__ __align__(16) __half g_P_r[(size_t)B_ * H_ * N_ * N_];

// ---------------------------------------------------------------------------
// helpers (portable sm_80+ PTX)
// ---------------------------------------------------------------------------
__device__ __forceinline__ uint32_t smem_u32(const void* p) {
    uint32_t a;
    asm("{ .reg .u64 t; cvta.to.shared.u64 t, %1; cvt.u32.u64 %0, t; }"
        : "=r"(a) : "l"(p));
    return a;
}

#define CP16(dst, src) \
    asm volatile("cp.async.cg.shared.global [%0], [%1], 16;" \
                 :: "r"(dst), "l"(src))
#define CP_COMMIT() asm volatile("cp.async.commit_group;" ::: "memory")
#define CP_WAIT1()  asm volatile("cp.async.wait_group 1;"  ::: "memory")

#define LDSM4(r, a)                                                           \
    asm volatile("ldmatrix.sync.aligned.m8n8.x4.shared.b16 {%0,%1,%2,%3}, [%4];" \
                 : "=r"((r)[0]), "=r"((r)[1]), "=r"((r)[2]), "=r"((r)[3])     \
                 : "r"(a))

#define MMA(c, a, b)                                                          \
    asm volatile("mma.sync.aligned.m16n8k16.row.col.f32.f16.f16.f32 "         \
                 "{%0,%1,%2,%3},{%4,%5,%6,%7},{%8,%9},{%0,%1,%2,%3};"         \
                 : "+f"((c)[0]), "+f"((c)[1]), "+f"((c)[2]), "+f"((c)[3])     \
                 : "r"((a)[0]), "r"((a)[1]), "r"((a)[2]), "r"((a)[3]),        \
                   "r"((b)[0]), "r"((b)[1]))

// swizzle within a 128B row
#define SWZC(row, colB) ((uint32_t)(colB) ^ (((uint32_t)(row) & 7u) << 4))

// smem: 128B rows = [hi k0..31 | lo k0..31], K-chunk 32, 3 stages
#define AT_B   (128 * 128)           // 16384
#define BT_B   (64 * 128)            // 8192
#define STG_B  (AT_B + BT_B)         // 24576
#define OFF_B  AT_B
#define NSTG   3
#define GSMEM  (NSTG * STG_B)        // 73728

// ---------------------------------------------------------------------------
// Split-fp16 mma.sync GEMM (NT): C[m,n] = alpha * sum_k A[m,k]B[n,k]
// A = Ah + Ar, B = Bh (+ Br if TERMS==3).
// TERMS 3: ah*bh + ah*bl + al*bh.  TERMS 2: ah*bh + al*bh  (= A*Bh).
// CTA tile 128x64, 8 warps (4m x 2n), warp tile 32x32, 3 CTAs/SM target.
// EPI 0: fp32 C.  EPI 1: (h, r) fp16 pair.
// ---------------------------------------------------------------------------
template <int EPI, int TERMS>
__global__ __launch_bounds__(256, 3) void gemm_mma(
    const __half* __restrict__ Ahi, const __half* __restrict__ Alo,
    int ldA, size_t aBatch, int aDiv, int aMod,
    const __half* __restrict__ Bhi, const __half* __restrict__ Blo,
    int ldB, size_t bBatch, int bDiv, int bMod,
    int K,
    float* __restrict__ Cf,
    __half* __restrict__ Chi, __half* __restrict__ Clo,
    int ldC, size_t cBatch, float alpha)
{
    extern __shared__ char smem[];
    const uint32_t sb = smem_u32(smem);
    const int tid = threadIdx.x;
    const int wid = tid >> 5, lane = tid & 31;
    const int wm = (wid >> 1) * 32;
    const int wn = (wid & 1) * 32;
    const int z = blockIdx.z;
    const int m0 = blockIdx.y * 128;
    const int n0 = blockIdx.x * 64;

    Ahi += (size_t)((z / aDiv) % aMod) * aBatch;
    Alo += (size_t)((z / aDiv) % aMod) * aBatch;
    Bhi += (size_t)((z / bDiv) % bMod) * bBatch;
    if (TERMS == 3) Blo += (size_t)((z / bDiv) % bMod) * bBatch;

    const int total = K / 32;

#define LOAD_CHUNK(ch) do {                                                   \
        const int k0_ = (ch) * 32;                                            \
        const uint32_t bb_ = sb + ((ch) % NSTG) * STG_B;                      \
        _Pragma("unroll")                                                     \
        for (int it = 0; it < 4; it++) {   /* A: 128 rows x 8 pieces */       \
            const int idx = tid + it * 256;                                   \
            const int row = idx >> 3;                                         \
            const int p = idx & 7;                                            \
            const __half* src = (p < 4) ? Ahi : Alo;                          \
            const uint32_t d = row * 128 + SWZC(row, p * 16);                 \
            CP16(bb_ + d, (const char*)(src + (size_t)(m0 + row) * ldA        \
                                        + k0_ + (p & 3) * 8));                \
        }                                                                     \
        if (TERMS == 3) {                                                     \
            _Pragma("unroll")                                                 \
            for (int it = 0; it < 2; it++) {  /* B: 64 rows x 8 pieces */     \
                const int idx = tid + it * 256;                               \
                const int row = idx >> 3;                                     \
                const int p = idx & 7;                                        \
                const __half* src = (p < 4) ? Bhi : Blo;                      \
                const uint32_t d = OFF_B + row * 128 + SWZC(row, p * 16);     \
                CP16(bb_ + d, (const char*)(src + (size_t)(n0 + row) * ldB    \
                                            + k0_ + (p & 3) * 8));            \
            }                                                                 \
        } else {                           /* B: hi only, 64 rows x 4 */      \
            const int row = tid >> 2;                                         \
            const int p = tid & 3;                                            \
            const uint32_t d = OFF_B + row * 128 + SWZC(row, p * 16);         \
            CP16(bb_ + d, (const char*)(Bhi + (size_t)(n0 + row) * ldB        \
                                        + k0_ + p * 8));                      \
        }                                                                     \
    } while (0)

    float acc[2][4][4];
#pragma unroll
    for (int i = 0; i < 2; i++)
#pragma unroll
        for (int j = 0; j < 4; j++)
#pragma unroll
            for (int r = 0; r < 4; r++) acc[i][j][r] = 0.f;

    LOAD_CHUNK(0); CP_COMMIT();
    LOAD_CHUNK(1); CP_COMMIT();

    const int aRow = lane & 15;
    const int aCol0 = lane & 16;
    const int bRow0 = (lane & 7) + ((lane >> 4) & 1) * 8;
    const int bCol0 = ((lane >> 3) & 1) * 16;

    for (int ch = 0; ch < total; ch++) {
        CP_WAIT1();
        __syncthreads();
        if (ch + 2 < total) LOAD_CHUNK(ch + 2);
        CP_COMMIT();

        const uint32_t bb = sb + (ch % NSTG) * STG_B;

#pragma unroll
        for (int ks = 0; ks < 2; ks++) {
            uint32_t ah[2][4], al[2][4], bh[4][2], bl[4][2];
#pragma unroll
            for (int i = 0; i < 2; i++) {
                const int row = wm + i * 16 + aRow;
                const int colH = ks * 32 + aCol0;
                const uint32_t ra = bb + row * 128;
                LDSM4(ah[i], ra + SWZC(row, colH));
                LDSM4(al[i], ra + SWZC(row, colH + 64));
            }
#pragma unroll
            for (int jj = 0; jj < 2; jj++) {
                const int row = wn + jj * 16 + bRow0;
                const int colH = ks * 32 + bCol0;
                const uint32_t rb = bb + OFF_B + row * 128;
                LDSM4(&bh[jj * 2][0], rb + SWZC(row, colH));
                if (TERMS == 3) LDSM4(&bl[jj * 2][0], rb + SWZC(row, colH + 64));
            }
#pragma unroll
            for (int i = 0; i < 2; i++)
#pragma unroll
                for (int j = 0; j < 4; j++) {
                    MMA(acc[i][j], ah[i], bh[j]);
                    if (TERMS == 3) MMA(acc[i][j], ah[i], bl[j]);
                    MMA(acc[i][j], al[i], bh[j]);
                }
        }
    }
#undef LOAD_CHUNK

    // ---- epilogue ----
    const int cr = lane >> 2, cc = (lane & 3) * 2;
#pragma unroll
    for (int i = 0; i < 2; i++) {
        const int r0 = m0 + wm + i * 16 + cr;
#pragma unroll
        for (int j = 0; j < 4; j++) {
            const int col = n0 + wn + j * 8 + cc;
            const size_t o0 = (size_t)z * cBatch + (size_t)r0 * ldC + col;
            const size_t o1 = o0 + (size_t)8 * ldC;
            float v0 = acc[i][j][0] * alpha, v1 = acc[i][j][1] * alpha;
            float v2 = acc[i][j][2] * alpha, v3 = acc[i][j][3] * alpha;
            if (EPI == 0) {
                Cf[o0] = v0; Cf[o0 + 1] = v1;
                Cf[o1] = v2; Cf[o1 + 1] = v3;
            } else {
                __half h0 = __float2half_rn(v0), h1 = __float2half_rn(v1);
                __half h2 = __float2half_rn(v2), h3 = __float2half_rn(v3);
                Chi[o0] = h0; Chi[o0 + 1] = h1;
                Chi[o1] = h2; Chi[o1 + 1] = h3;
                Clo[o0] = __float2half_rn(v0 - __half2float(h0));
                Clo[o0 + 1] = __float2half_rn(v1 - __half2float(h1));
                Clo[o1] = __float2half_rn(v2 - __half2float(h2));
                Clo[o1 + 1] = __float2half_rn(v3 - __half2float(h3));
            }
        }
    }
}

// ---------------------------------------------------------------------------
// Split x -> xs (h/r, [B,N,D]) and xt (h only, [B,D,N])
// ---------------------------------------------------------------------------
__global__ __launch_bounds__(256) void split_x_kernel(const float* __restrict__ x) {
    __shared__ float t[32][33];
    const int b = blockIdx.z;
    const int d0 = blockIdx.x * 32, n0 = blockIdx.y * 32;
    const int tx = threadIdx.x & 31, ty = threadIdx.x >> 5;

    for (int i = ty; i < 32; i += 8)
        t[i][tx] = x[(size_t)b * N_ * D_ + (size_t)(n0 + i) * D_ + d0 + tx];
    __syncthreads();

    for (int i = ty; i < 32; i += 8) {
        float v = t[i][tx];
        __half h = __float2half_rn(v);
        size_t o = (size_t)b * N_ * D_ + (size_t)(n0 + i) * D_ + d0 + tx;
        g_xs_h[o] = h; g_xs_r[o] = __float2half_rn(v - __half2float(h));
    }
    for (int i = ty; i < 32; i += 8) {
        float v = t[tx][i];
        size_t o = (size_t)b * D_ * N_ + (size_t)(d0 + i) * N_ + n0 + tx;
        g_xt_h[o] = __float2half_rn(v);
    }
}

__global__ __launch_bounds__(256) void split_w_kernel(const float* __restrict__ W) {
    __shared__ float t[32][33];
    const int h = blockIdx.z;
    const int e0 = blockIdx.x * 32, d0 = blockIdx.y * 32;
    const int tx = threadIdx.x & 31, ty = threadIdx.x >> 5;

    for (int i = ty; i < 32; i += 8)
        t[i][tx] = W[(size_t)h * D_ * D_ + (size_t)(d0 + i) * D_ + e0 + tx];
    __syncthreads();

    for (int i = ty; i < 32; i += 8) {
        float v = t[tx][i];   // W[d0+tx][e0+i]
        __half hh = __float2half_rn(v);
        size_t o = (size_t)h * D_ * D_ + (size_t)(e0 + i) * D_ + d0 + tx;
        g_Wt_h[o] = hh; g_Wt_r[o] = __float2half_rn(v - __half2float(hh));
    }
}

// ---------------------------------------------------------------------------
// Softmax over rows of g_S; writes h/r fp16 P
// ---------------------------------------------------------------------------
__global__ __launch_bounds__(256) void softmax_split_kernel() {
    const size_t row = blockIdx.x;
    const float* p = g_S + row * N_;
    const int tid = threadIdx.x;
    __shared__ float red[8];

    float4 v = *(const float4*)&p[tid * 4];
    float m = fmaxf(fmaxf(v.x, v.y), fmaxf(v.z, v.w));
#pragma unroll
    for (int o = 16; o; o >>= 1) m = fmaxf(m, __shfl_xor_sync(0xFFFFFFFFu, m, o));
    if ((tid & 31) == 0) red[tid >> 5] = m;
    __syncthreads();
    float bm = red[0];
#pragma unroll
    for (int i = 1; i < 8; i++) bm = fmaxf(bm, red[i]);
    __syncthreads();

    v.x = __expf(v.x - bm); v.y = __expf(v.y - bm);
    v.z = __expf(v.z - bm); v.w = __expf(v.w - bm);
    float s = v.x + v.y + v.z + v.w;
#pragma unroll
    for (int o = 16; o; o >>= 1) s += __shfl_xor_sync(0xFFFFFFFFu, s, o);
    if ((tid & 31) == 0) red[tid >> 5] = s;
    __syncthreads();
    float bs = 0.f;
#pragma unroll
    for (int i = 0; i < 8; i++) bs += red[i];
    float inv = 1.0f / bs;

    float vals[4] = {v.x * inv, v.y * inv, v.z * inv, v.w * inv};
#pragma unroll
    for (int j = 0; j < 4; j++) {
        __half h = __float2half_rn(vals[j]);
        g_P_h[row * N_ + tid * 4 + j] = h;
        g_P_r[row * N_ + tid * 4 + j] = __float2half_rn(vals[j] - __half2float(h));
    }
}

// ---------------------------------------------------------------------------
// out[b,n,d] = 0.25 * sum_h scratch[b*4+h, n, d]
// ---------------------------------------------------------------------------
__global__ __launch_bounds__(256) void reduce_heads_kernel(float* __restrict__ out) {
    const size_t i4 = ((size_t)blockIdx.x * 256 + threadIdx.x) * 4;
    const size_t b = i4 / ((size_t)N_ * D_);
    const size_t w = i4 % ((size_t)N_ * D_);
    const float* s = g_S + (b * 4) * (size_t)N_ * D_ + w;
    float4 v0 = *(const float4*)(s);
    float4 v1 = *(const float4*)(s + (size_t)N_ * D_);
    float4 v2 = *(const float4*)(s + 2 * (size_t)N_ * D_);
    float4 v3 = *(const float4*)(s + 3 * (size_t)N_ * D_);
    float4 r;
    r.x = 0.25f * (v0.x + v1.x + v2.x + v3.x);
    r.y = 0.25f * (v0.y + v1.y + v2.y + v3.y);
    r.z = 0.25f * (v0.z + v1.z + v2.z + v3.z);
    r.w = 0.25f * (v0.w + v1.w + v2.w + v3.w);
    *(float4*)&out[i4] = r;
}

// ---------------------------------------------------------------------------
extern "C" void kernel_launch(void* const* d_in, const int* in_sizes, int n_in,
                              void* d_out, int out_size) {
    const float* x = (const float*)d_in[0];   // [8,1024,512]
    const float* W = (const float*)d_in[1];   // [4,512,512]
    float* out = (float*)d_out;               // [8,1024,512]

    cudaFuncSetAttribute(gemm_mma<0, 3>, cudaFuncAttributeMaxDynamicSharedMemorySize, GSMEM);
    cudaFuncSetAttribute(gemm_mma<1, 3>, cudaFuncAttributeMaxDynamicSharedMemorySize, GSMEM);
    cudaFuncSetAttribute(gemm_mma<0, 2>, cudaFuncAttributeMaxDynamicSharedMemorySize, GSMEM);

    __half *xs_h, *xs_r, *xt_h, *Wt_h, *Wt_r, *Y_h, *Y_r, *P_h, *P_r;
    float* Sf;
    cudaGetSymbolAddress((void**)&xs_h, g_xs_h);
    cudaGetSymbolAddress((void**)&xs_r, g_xs_r);
    cudaGetSymbolAddress((void**)&xt_h, g_xt_h);
    cudaGetSymbolAddress((void**)&Wt_h, g_Wt_h);
    cudaGetSymbolAddress((void**)&Wt_r, g_Wt_r);
    cudaGetSymbolAddress((void**)&Y_h, g_Y_h);
    cudaGetSymbolAddress((void**)&Y_r, g_Y_r);
    cudaGetSymbolAddress((void**)&P_h, g_P_h);
    cudaGetSymbolAddress((void**)&P_r, g_P_r);
    cudaGetSymbolAddress((void**)&Sf, g_S);

    const float SCALE = 0.04419417382415922f;   // 512^-0.5

    split_x_kernel<<<dim3(D_ / 32, N_ / 32, B_), 256>>>(x);
    split_w_kernel<<<dim3(D_ / 32, D_ / 32, H_), 256>>>(W);

    // K1: Y[b,h] = xs[b] @ Wt[h]^T  (3-term) -> fp16 h/r Y
    gemm_mma<1, 3><<<dim3(D_ / 64, N_ / 128, B_ * H_), 256, GSMEM>>>(
        xs_h, xs_r, D_, (size_t)N_ * D_, 4, 8,
        Wt_h, Wt_r, D_, (size_t)D_ * D_, 1, 4,
        D_,
        nullptr, Y_h, Y_r, D_, (size_t)N_ * D_, 1.0f);

    // K2: S[b,h] = scale * Y[b,h] @ xs[b]^T  (3-term) -> fp32
    gemm_mma<0, 3><<<dim3(N_ / 64, N_ / 128, B_ * H_), 256, GSMEM>>>(
        Y_h, Y_r, D_, (size_t)N_ * D_, 1, 32,
        xs_h, xs_r, D_, (size_t)N_ * D_, 4, 8,
        D_,
        Sf, nullptr, nullptr, N_, (size_t)N_ * N_, SCALE);

    softmax_split_kernel<<<B_ * H_ * N_, 256>>>();

    // K4: scratch[b,h] = P[b,h] @ xt[b]^T  (2-term) -> fp32 scratch (g_S reuse)
    gemm_mma<0, 2><<<dim3(D_ / 64, N_ / 128, B_ * H_), 256, GSMEM>>>(
        P_h, P_r, N_, (size_t)N_ * N_, 1, 32,
        xt_h, nullptr, N_, (size_t)D_ * N_, 4, 8,
        N_,
        Sf, nullptr, nullptr, D_, (size_t)N_ * D_, 1.0f);

    // out = 0.25 * sum_h scratch
    reduce_heads_kernel<<<(B_ * N_ * D_) / (4 * 256), 256>>>(out);
}

// round 9
// speedup vs baseline: 3.5840x; 1.1056x over previous
#include <cuda_runtime.h>
#include <cuda_fp16.h>
#include <cstdint>
#include <math.h>

#define B_ 8
#define N_ 1024
#define D_ 512
#define H_ 4

// ---------------------------------------------------------------------------
// Scratch (device globals; no allocation allowed)
// ---------------------------------------------------------------------------
__device__ __align__(16) __half g_xs_h[(size_t)B_ * N_ * D_];
__device__ __align__(16) __half g_xs_r[(size_t)B_ * N_ * D_];
__device__ __align__(16) __half g_xt_h[(size_t)B_ * D_ * N_];
__device__ __align__(16) __half g_Wt_h[(size_t)H_ * D_ * D_];
__device__ __align__(16) __half g_Wt_r[(size_t)H_ * D_ * D_];
__device__ __align__(16) __half g_Y_h[(size_t)B_ * H_ * N_ * D_];
__device__ __align__(16) __half g_Y_r[(size_t)B_ * H_ * N_ * D_];
__device__ __align__(16) float  g_S  [(size_t)B_ * H_ * N_ * N_];  // also K4 scratch
__device__ __align__(16) __half g_P_h[(size_t)B_ * H_ * N_ * N_];
__device__ __align__(16) __half g_P_r[(size_t)B_ * H_ * N_ * N_];

// ---------------------------------------------------------------------------
// helpers (portable sm_80+ PTX)
// ---------------------------------------------------------------------------
__device__ __forceinline__ uint32_t smem_u32(const void* p) {
    uint32_t a;
    asm("{ .reg .u64 t; cvta.to.shared.u64 t, %1; cvt.u32.u64 %0, t; }"
        : "=r"(a) : "l"(p));
    return a;
}

#define CP16(dst, src) \
    asm volatile("cp.async.cg.shared.global [%0], [%1], 16;" \
                 :: "r"(dst), "l"(src))
#define CP_COMMIT() asm volatile("cp.async.commit_group;" ::: "memory")
#define CP_WAIT1()  asm volatile("cp.async.wait_group 1;"  ::: "memory")

#define LDSM4(r, a)                                                           \
    asm volatile("ldmatrix.sync.aligned.m8n8.x4.shared.b16 {%0,%1,%2,%3}, [%4];" \
                 : "=r"((r)[0]), "=r"((r)[1]), "=r"((r)[2]), "=r"((r)[3])     \
                 : "r"(a))

#define MMA(c, a, b)                                                          \
    asm volatile("mma.sync.aligned.m16n8k16.row.col.f32.f16.f16.f32 "         \
                 "{%0,%1,%2,%3},{%4,%5,%6,%7},{%8,%9},{%0,%1,%2,%3};"         \
                 : "+f"((c)[0]), "+f"((c)[1]), "+f"((c)[2]), "+f"((c)[3])     \
                 : "r"((a)[0]), "r"((a)[1]), "r"((a)[2]), "r"((a)[3]),        \
                   "r"((b)[0]), "r"((b)[1]))

// swizzle within a 128B row
#define SWZC(row, colB) ((uint32_t)(colB) ^ (((uint32_t)(row) & 7u) << 4))

// smem: 128B rows = [hi k0..31 | lo k0..31], K-chunk 32, 3 stages
// A: 128 rows, B: 128 rows
#define AT_B   (128 * 128)           // 16384
#define BT_B   (128 * 128)           // 16384
#define STG_B  (AT_B + BT_B)         // 32768
#define OFF_B  AT_B
#define NSTG   3
#define GSMEM  (NSTG * STG_B)        // 98304

// ---------------------------------------------------------------------------
// Split-fp16 mma.sync GEMM (NT): C[m,n] = alpha * sum_k A[m,k]B[n,k]
// A = Ah + Ar, B = Bh (+ Br if TERMS==3).
// TERMS 3: ah*bh + ah*bl + al*bh.  TERMS 2: ah*bh + al*bh  (= A*Bh).
// CTA tile 128x128, 8 warps (2m x 4n), warp tile 64x32, K-chunk 32,
// 3-stage cp.async ring, 2 CTAs/SM.
// EPI 0: fp32 C.  EPI 1: (h, r) fp16 pair.
// ---------------------------------------------------------------------------
template <int EPI, int TERMS>
__global__ __launch_bounds__(256, 2) void gemm_mma(
    const __half* __restrict__ Ahi, const __half* __restrict__ Alo,
    int ldA, size_t aBatch, int aDiv, int aMod,
    const __half* __restrict__ Bhi, const __half* __restrict__ Blo,
    int ldB, size_t bBatch, int bDiv, int bMod,
    int K,
    float* __restrict__ Cf,
    __half* __restrict__ Chi, __half* __restrict__ Clo,
    int ldC, size_t cBatch, float alpha)
{
    extern __shared__ char smem[];
    const uint32_t sb = smem_u32(smem);
    const int tid = threadIdx.x;
    const int wid = tid >> 5, lane = tid & 31;
    const int wm = (wid >> 2) * 64;     // 2 m-groups
    const int wn = (wid & 3) * 32;      // 4 n-groups
    const int z = blockIdx.z;
    const int m0 = blockIdx.y * 128;
    const int n0 = blockIdx.x * 128;

    Ahi += (size_t)((z / aDiv) % aMod) * aBatch;
    Alo += (size_t)((z / aDiv) % aMod) * aBatch;
    Bhi += (size_t)((z / bDiv) % bMod) * bBatch;
    if (TERMS == 3) Blo += (size_t)((z / bDiv) % bMod) * bBatch;

    const int total = K / 32;

#define LOAD_CHUNK(ch, stg) do {                                              \
        const int k0_ = (ch) * 32;                                            \
        const uint32_t bb_ = sb + (stg) * STG_B;                              \
        _Pragma("unroll")                                                     \
        for (int it = 0; it < 4; it++) {   /* A: 128 rows x 8 pieces */       \
            const int idx = tid + it * 256;                                   \
            const int row = idx >> 3;                                         \
            const int p = idx & 7;                                            \
            const __half* src = (p < 4) ? Ahi : Alo;                          \
            const uint32_t d = row * 128 + SWZC(row, p * 16);                 \
            CP16(bb_ + d, (const char*)(src + (size_t)(m0 + row) * ldA        \
                                        + k0_ + (p & 3) * 8));                \
        }                                                                     \
        if (TERMS == 3) {                                                     \
            _Pragma("unroll")                                                 \
            for (int it = 0; it < 4; it++) {  /* B: 128 rows x 8 pieces */    \
                const int idx = tid + it * 256;                               \
                const int row = idx >> 3;                                     \
                const int p = idx & 7;                                        \
                const __half* src = (p < 4) ? Bhi : Blo;                      \
                const uint32_t d = OFF_B + row * 128 + SWZC(row, p * 16);     \
                CP16(bb_ + d, (const char*)(src + (size_t)(n0 + row) * ldB    \
                                            + k0_ + (p & 3) * 8));            \
            }                                                                 \
        } else {                           /* B: hi only, 128 rows x 4 */     \
            _Pragma("unroll")                                                 \
            for (int it = 0; it < 2; it++) {                                  \
                const int idx = tid + it * 256;                               \
                const int row = idx >> 2;                                     \
                const int p = idx & 3;                                        \
                const uint32_t d = OFF_B + row * 128 + SWZC(row, p * 16);     \
                CP16(bb_ + d, (const char*)(Bhi + (size_t)(n0 + row) * ldB    \
                                            + k0_ + p * 8));                  \
            }                                                                 \
        }                                                                     \
    } while (0)

    float acc[4][4][4];
#pragma unroll
    for (int i = 0; i < 4; i++)
#pragma unroll
        for (int j = 0; j < 4; j++)
#pragma unroll
            for (int r = 0; r < 4; r++) acc[i][j][r] = 0.f;

    LOAD_CHUNK(0, 0); CP_COMMIT();
    LOAD_CHUNK(1, 1); CP_COMMIT();

    // per-lane LDSM geometry
    const int aRow = lane & 15;                              // A: 16x16 frags
    const int aCol0 = lane & 16;                             // 0 / 16 bytes
    const int bRow0 = (lane & 7) + ((lane >> 4) & 1) * 8;    // B: 16-row pair
    const int bCol0 = ((lane >> 3) & 1) * 16;

    int stg = 0;                // stage holding chunk `ch`
    for (int ch = 0; ch < total; ch++) {
        CP_WAIT1();
        __syncthreads();
        {
            int nstg = stg + 2; if (nstg >= NSTG) nstg -= NSTG;
            if (ch + 2 < total) { LOAD_CHUNK(ch + 2, nstg); }
            CP_COMMIT();
        }

        const uint32_t bb = sb + stg * STG_B;

#pragma unroll
        for (int ks = 0; ks < 2; ks++) {
            uint32_t bh[4][2], bl[4][2];
            const int colH = ks * 32;
#pragma unroll
            for (int jj = 0; jj < 2; jj++) {
                const int row = wn + jj * 16 + bRow0;
                const uint32_t rb = bb + OFF_B + row * 128;
                LDSM4(&bh[jj * 2][0], rb + SWZC(row, colH + bCol0));
                if (TERMS == 3) LDSM4(&bl[jj * 2][0], rb + SWZC(row, colH + bCol0 + 64));
            }
            // stream A tiles, one ahead
            uint32_t ahc[4], alc[4], ahn[4], aln[4];
            {
                const int row = wm + aRow;
                const uint32_t ra = bb + row * 128;
                LDSM4(ahc, ra + SWZC(row, colH + aCol0));
                LDSM4(alc, ra + SWZC(row, colH + aCol0 + 64));
            }
#pragma unroll
            for (int i = 0; i < 4; i++) {
                if (i < 3) {
                    const int row = wm + (i + 1) * 16 + aRow;
                    const uint32_t ra = bb + row * 128;
                    LDSM4(ahn, ra + SWZC(row, colH + aCol0));
                    LDSM4(aln, ra + SWZC(row, colH + aCol0 + 64));
                }
#pragma unroll
                for (int j = 0; j < 4; j++) {
                    MMA(acc[i][j], ahc, bh[j]);
                    if (TERMS == 3) MMA(acc[i][j], ahc, bl[j]);
                    MMA(acc[i][j], alc, bh[j]);
                }
#pragma unroll
                for (int r = 0; r < 4; r++) { ahc[r] = ahn[r]; alc[r] = aln[r]; }
            }
        }
        stg = stg + 1; if (stg >= NSTG) stg = 0;
    }
#undef LOAD_CHUNK

    // ---- epilogue ----
    const int cr = lane >> 2, cc = (lane & 3) * 2;
#pragma unroll
    for (int i = 0; i < 4; i++) {
        const int r0 = m0 + wm + i * 16 + cr;
#pragma unroll
        for (int j = 0; j < 4; j++) {
            const int col = n0 + wn + j * 8 + cc;
            const size_t o0 = (size_t)z * cBatch + (size_t)r0 * ldC + col;
            const size_t o1 = o0 + (size_t)8 * ldC;
            float v0 = acc[i][j][0] * alpha, v1 = acc[i][j][1] * alpha;
            float v2 = acc[i][j][2] * alpha, v3 = acc[i][j][3] * alpha;
            if (EPI == 0) {
                Cf[o0] = v0; Cf[o0 + 1] = v1;
                Cf[o1] = v2; Cf[o1 + 1] = v3;
            } else {
                __half h0 = __float2half_rn(v0), h1 = __float2half_rn(v1);
                __half h2 = __float2half_rn(v2), h3 = __float2half_rn(v3);
                Chi[o0] = h0; Chi[o0 + 1] = h1;
                Chi[o1] = h2; Chi[o1 + 1] = h3;
                Clo[o0] = __float2half_rn(v0 - __half2float(h0));
                Clo[o0 + 1] = __float2half_rn(v1 - __half2float(h1));
                Clo[o1] = __float2half_rn(v2 - __half2float(h2));
                Clo[o1 + 1] = __float2half_rn(v3 - __half2float(h3));
            }
        }
    }
}

// ---------------------------------------------------------------------------
// Split x -> xs (h/r, [B,N,D]) and xt (h only, [B,D,N])
// ---------------------------------------------------------------------------
__global__ __launch_bounds__(256) void split_x_kernel(const float* __restrict__ x) {
    __shared__ float t[32][33];
    const int b = blockIdx.z;
    const int d0 = blockIdx.x * 32, n0 = blockIdx.y * 32;
    const int tx = threadIdx.x & 31, ty = threadIdx.x >> 5;

    for (int i = ty; i < 32; i += 8)
        t[i][tx] = x[(size_t)b * N_ * D_ + (size_t)(n0 + i) * D_ + d0 + tx];
    __syncthreads();

    for (int i = ty; i < 32; i += 8) {
        float v = t[i][tx];
        __half h = __float2half_rn(v);
        size_t o = (size_t)b * N_ * D_ + (size_t)(n0 + i) * D_ + d0 + tx;
        g_xs_h[o] = h; g_xs_r[o] = __float2half_rn(v - __half2float(h));
    }
    for (int i = ty; i < 32; i += 8) {
        float v = t[tx][i];
        size_t o = (size_t)b * D_ * N_ + (size_t)(d0 + i) * N_ + n0 + tx;
        g_xt_h[o] = __float2half_rn(v);
    }
}

__global__ __launch_bounds__(256) void split_w_kernel(const float* __restrict__ W) {
    __shared__ float t[32][33];
    const int h = blockIdx.z;
    const int e0 = blockIdx.x * 32, d0 = blockIdx.y * 32;
    const int tx = threadIdx.x & 31, ty = threadIdx.x >> 5;

    for (int i = ty; i < 32; i += 8)
        t[i][tx] = W[(size_t)h * D_ * D_ + (size_t)(d0 + i) * D_ + e0 + tx];
    __syncthreads();

    for (int i = ty; i < 32; i += 8) {
        float v = t[tx][i];   // W[d0+tx][e0+i]
        __half hh = __float2half_rn(v);
        size_t o = (size_t)h * D_ * D_ + (size_t)(e0 + i) * D_ + d0 + tx;
        g_Wt_h[o] = hh; g_Wt_r[o] = __float2half_rn(v - __half2float(hh));
    }
}

// ---------------------------------------------------------------------------
// Softmax over rows of g_S; writes h/r fp16 P
// ---------------------------------------------------------------------------
__global__ __launch_bounds__(256) void softmax_split_kernel() {
    const size_t row = blockIdx.x;
    const float* p = g_S + row * N_;
    const int tid = threadIdx.x;
    __shared__ float red[8];

    float4 v = *(const float4*)&p[tid * 4];
    float m = fmaxf(fmaxf(v.x, v.y), fmaxf(v.z, v.w));
#pragma unroll
    for (int o = 16; o; o >>= 1) m = fmaxf(m, __shfl_xor_sync(0xFFFFFFFFu, m, o));
    if ((tid & 31) == 0) red[tid >> 5] = m;
    __syncthreads();
    float bm = red[0];
#pragma unroll
    for (int i = 1; i < 8; i++) bm = fmaxf(bm, red[i]);
    __syncthreads();

    v.x = __expf(v.x - bm); v.y = __expf(v.y - bm);
    v.z = __expf(v.z - bm); v.w = __expf(v.w - bm);
    float s = v.x + v.y + v.z + v.w;
#pragma unroll
    for (int o = 16; o; o >>= 1) s += __shfl_xor_sync(0xFFFFFFFFu, s, o);
    if ((tid & 31) == 0) red[tid >> 5] = s;
    __syncthreads();
    float bs = 0.f;
#pragma unroll
    for (int i = 0; i < 8; i++) bs += red[i];
    float inv = 1.0f / bs;

    float vals[4] = {v.x * inv, v.y * inv, v.z * inv, v.w * inv};
#pragma unroll
    for (int j = 0; j < 4; j++) {
        __half h = __float2half_rn(vals[j]);
        g_P_h[row * N_ + tid * 4 + j] = h;
        g_P_r[row * N_ + tid * 4 + j] = __float2half_rn(vals[j] - __half2float(h));
    }
}

// ---------------------------------------------------------------------------
// out[b,n,d] = 0.25 * sum_h scratch[b*4+h, n, d]
// ---------------------------------------------------------------------------
__global__ __launch_bounds__(256) void reduce_heads_kernel(float* __restrict__ out) {
    const size_t i4 = ((size_t)blockIdx.x * 256 + threadIdx.x) * 4;
    const size_t b = i4 / ((size_t)N_ * D_);
    const size_t w = i4 % ((size_t)N_ * D_);
    const float* s = g_S + (b * 4) * (size_t)N_ * D_ + w;
    float4 v0 = *(const float4*)(s);
    float4 v1 = *(const float4*)(s + (size_t)N_ * D_);
    float4 v2 = *(const float4*)(s + 2 * (size_t)N_ * D_);
    float4 v3 = *(const float4*)(s + 3 * (size_t)N_ * D_);
    float4 r;
    r.x = 0.25f * (v0.x + v1.x + v2.x + v3.x);
    r.y = 0.25f * (v0.y + v1.y + v2.y + v3.y);
    r.z = 0.25f * (v0.z + v1.z + v2.z + v3.z);
    r.w = 0.25f * (v0.w + v1.w + v2.w + v3.w);
    *(float4*)&out[i4] = r;
}

// ---------------------------------------------------------------------------
extern "C" void kernel_launch(void* const* d_in, const int* in_sizes, int n_in,
                              void* d_out, int out_size) {
    const float* x = (const float*)d_in[0];   // [8,1024,512]
    const float* W = (const float*)d_in[1];   // [4,512,512]
    float* out = (float*)d_out;               // [8,1024,512]

    cudaFuncSetAttribute(gemm_mma<0, 3>, cudaFuncAttributeMaxDynamicSharedMemorySize, GSMEM);
    cudaFuncSetAttribute(gemm_mma<1, 3>, cudaFuncAttributeMaxDynamicSharedMemorySize, GSMEM);
    cudaFuncSetAttribute(gemm_mma<0, 2>, cudaFuncAttributeMaxDynamicSharedMemorySize, GSMEM);

    __half *xs_h, *xs_r, *xt_h, *Wt_h, *Wt_r, *Y_h, *Y_r, *P_h, *P_r;
    float* Sf;
    cudaGetSymbolAddress((void**)&xs_h, g_xs_h);
    cudaGetSymbolAddress((void**)&xs_r, g_xs_r);
    cudaGetSymbolAddress((void**)&xt_h, g_xt_h);
    cudaGetSymbolAddress((void**)&Wt_h, g_Wt_h);
    cudaGetSymbolAddress((void**)&Wt_r, g_Wt_r);
    cudaGetSymbolAddress((void**)&Y_h, g_Y_h);
    cudaGetSymbolAddress((void**)&Y_r, g_Y_r);
    cudaGetSymbolAddress((void**)&P_h, g_P_h);
    cudaGetSymbolAddress((void**)&P_r, g_P_r);
    cudaGetSymbolAddress((void**)&Sf, g_S);

    const float SCALE = 0.04419417382415922f;   // 512^-0.5

    split_x_kernel<<<dim3(D_ / 32, N_ / 32, B_), 256>>>(x);
    split_w_kernel<<<dim3(D_ / 32, D_ / 32, H_), 256>>>(W);

    // K1: Y[b,h] = xs[b] @ Wt[h]^T  (3-term) -> fp16 h/r Y
    gemm_mma<1, 3><<<dim3(D_ / 128, N_ / 128, B_ * H_), 256, GSMEM>>>(
        xs_h, xs_r, D_, (size_t)N_ * D_, 4, 8,
        Wt_h, Wt_r, D_, (size_t)D_ * D_, 1, 4,
        D_,
        nullptr, Y_h, Y_r, D_, (size_t)N_ * D_, 1.0f);

    // K2: S[b,h] = scale * Y[b,h] @ xs[b]^T  (3-term) -> fp32
    gemm_mma<0, 3><<<dim3(N_ / 128, N_ / 128, B_ * H_), 256, GSMEM>>>(
        Y_h, Y_r, D_, (size_t)N_ * D_, 1, 32,
        xs_h, xs_r, D_, (size_t)N_ * D_, 4, 8,
        D_,
        Sf, nullptr, nullptr, N_, (size_t)N_ * N_, SCALE);

    softmax_split_kernel<<<B_ * H_ * N_, 256>>>();

    // K4: scratch[b,h] = P[b,h] @ xt[b]^T  (2-term) -> fp32 scratch (g_S reuse)
    gemm_mma<0, 2><<<dim3(D_ / 128, N_ / 128, B_ * H_), 256, GSMEM>>>(
        P_h, P_r, N_, (size_t)N_ * N_, 1, 32,
        xt_h, nullptr, N_, (size_t)D_ * N_, 4, 8,
        N_,
        Sf, nullptr, nullptr, D_, (size_t)N_ * D_, 1.0f);

    // out = 0.25 * sum_h scratch
    reduce_heads_kernel<<<(B_ * N_ * D_) / (4 * 256), 256>>>(out);
}

// round 10
// speedup vs baseline: 4.1380x; 1.1546x over previous
#include <cuda_runtime.h>
#include <cuda_fp16.h>
#include <cstdint>
#include <math.h>

#define B_ 8
#define N_ 1024
#define D_ 512
#define H_ 4

// ---------------------------------------------------------------------------
// Scratch (device globals; no allocation allowed)
// ---------------------------------------------------------------------------
__device__ __align__(16) __half g_xs_h[(size_t)B_ * N_ * D_];
__device__ __align__(16) __half g_xs_r[(size_t)B_ * N_ * D_];
__device__ __align__(16) __half g_xt_h[(size_t)B_ * D_ * N_];
__device__ __align__(16) __half g_Wt_h[(size_t)H_ * D_ * D_];
__device__ __align__(16) __half g_Wt_r[(size_t)H_ * D_ * D_];
__device__ __align__(16) __half g_Y_h[(size_t)B_ * H_ * N_ * D_];
__device__ __align__(16) __half g_Y_r[(size_t)B_ * H_ * N_ * D_];
__device__ __align__(16) float  g_S  [(size_t)B_ * H_ * N_ * N_];  // also K4 scratch
__device__ __align__(16) __half g_P_h[(size_t)B_ * H_ * N_ * N_];

// ---------------------------------------------------------------------------
// helpers (portable sm_80+ PTX)
// ---------------------------------------------------------------------------
__device__ __forceinline__ uint32_t smem_u32(const void* p) {
    uint32_t a;
    asm("{ .reg .u64 t; cvta.to.shared.u64 t, %1; cvt.u32.u64 %0, t; }"
        : "=r"(a) : "l"(p));
    return a;
}

#define CP16(dst, src) \
    asm volatile("cp.async.cg.shared.global [%0], [%1], 16;" \
                 :: "r"(dst), "l"(src))
#define CP_COMMIT() asm volatile("cp.async.commit_group;" ::: "memory")
#define CP_WAIT1()  asm volatile("cp.async.wait_group 1;"  ::: "memory")

#define LDSM4(r, a)                                                           \
    asm volatile("ldmatrix.sync.aligned.m8n8.x4.shared.b16 {%0,%1,%2,%3}, [%4];" \
                 : "=r"((r)[0]), "=r"((r)[1]), "=r"((r)[2]), "=r"((r)[3])     \
                 : "r"(a))

#define MMA(c, a, b)                                                          \
    asm volatile("mma.sync.aligned.m16n8k16.row.col.f32.f16.f16.f32 "         \
                 "{%0,%1,%2,%3},{%4,%5,%6,%7},{%8,%9},{%0,%1,%2,%3};"         \
                 : "+f"((c)[0]), "+f"((c)[1]), "+f"((c)[2]), "+f"((c)[3])     \
                 : "r"((a)[0]), "r"((a)[1]), "r"((a)[2]), "r"((a)[3]),        \
                   "r"((b)[0]), "r"((b)[1]))

// swizzle within a 128B row
#define SWZC(row, colB) ((uint32_t)(colB) ^ (((uint32_t)(row) & 7u) << 4))

// smem: 128B rows = [hi k0..31 | lo k0..31], K-chunk 32, 3 stages
#define AT_B   (128 * 128)           // 16384
#define BT_B   (128 * 128)           // 16384
#define STG_B  (AT_B + BT_B)         // 32768
#define OFF_B  AT_B
#define NSTG   3
#define GSMEM  (NSTG * STG_B)        // 98304

// ---------------------------------------------------------------------------
// Split-fp16 mma.sync GEMM (NT): C[m,n] = alpha * sum_k A[m,k]B[n,k]
// TERMS 3: ah*bh + ah*bl + al*bh  (A = Ah+Ar, B = Bh+Br)
// TERMS 1: ah*bh               (pure fp16)
// CTA tile 128x128, 8 warps (2m x 4n), warp tile 64x32, K-chunk 32,
// 3-stage cp.async ring, 2 CTAs/SM.
// EPI 0: fp32 C.  EPI 1: (h, r) fp16 pair.
// ---------------------------------------------------------------------------
template <int EPI, int TERMS>
__global__ __launch_bounds__(256, 2) void gemm_mma(
    const __half* __restrict__ Ahi, const __half* __restrict__ Alo,
    int ldA, size_t aBatch, int aDiv, int aMod,
    const __half* __restrict__ Bhi, const __half* __restrict__ Blo,
    int ldB, size_t bBatch, int bDiv, int bMod,
    int K,
    float* __restrict__ Cf,
    __half* __restrict__ Chi, __half* __restrict__ Clo,
    int ldC, size_t cBatch, float alpha)
{
    extern __shared__ char smem[];
    const uint32_t sb = smem_u32(smem);
    const int tid = threadIdx.x;
    const int wid = tid >> 5, lane = tid & 31;
    const int wm = (wid >> 2) * 64;     // 2 m-groups
    const int wn = (wid & 3) * 32;      // 4 n-groups
    const int z = blockIdx.z;
    const int m0 = blockIdx.y * 128;
    const int n0 = blockIdx.x * 128;

    Ahi += (size_t)((z / aDiv) % aMod) * aBatch;
    if (TERMS == 3) Alo += (size_t)((z / aDiv) % aMod) * aBatch;
    Bhi += (size_t)((z / bDiv) % bMod) * bBatch;
    if (TERMS == 3) Blo += (size_t)((z / bDiv) % bMod) * bBatch;

    const int total = K / 32;

#define LOAD_CHUNK(ch, stg) do {                                              \
        const int k0_ = (ch) * 32;                                            \
        const uint32_t bb_ = sb + (stg) * STG_B;                              \
        if (TERMS == 3) {                                                     \
            _Pragma("unroll")                                                 \
            for (int it = 0; it < 4; it++) {   /* A: 128 rows x 8 pieces */   \
                const int idx = tid + it * 256;                               \
                const int row = idx >> 3;                                     \
                const int p = idx & 7;                                        \
                const __half* src = (p < 4) ? Ahi : Alo;                      \
                const uint32_t d = row * 128 + SWZC(row, p * 16);             \
                CP16(bb_ + d, (const char*)(src + (size_t)(m0 + row) * ldA    \
                                            + k0_ + (p & 3) * 8));            \
            }                                                                 \
            _Pragma("unroll")                                                 \
            for (int it = 0; it < 4; it++) {  /* B: 128 rows x 8 pieces */    \
                const int idx = tid + it * 256;                               \
                const int row = idx >> 3;                                     \
                const int p = idx & 7;                                        \
                const __half* src = (p < 4) ? Bhi : Blo;                      \
                const uint32_t d = OFF_B + row * 128 + SWZC(row, p * 16);     \
                CP16(bb_ + d, (const char*)(src + (size_t)(n0 + row) * ldB    \
                                            + k0_ + (p & 3) * 8));            \
            }                                                                 \
        } else {                              /* hi only: 128 rows x 4 */     \
            _Pragma("unroll")                                                 \
            for (int it = 0; it < 2; it++) {                                  \
                const int idx = tid + it * 256;                               \
                const int row = idx >> 2;                                     \
                const int p = idx & 3;                                        \
                const uint32_t d = row * 128 + SWZC(row, p * 16);             \
                CP16(bb_ + d, (const char*)(Ahi + (size_t)(m0 + row) * ldA    \
                                            + k0_ + p * 8));                  \
            }                                                                 \
            _Pragma("unroll")                                                 \
            for (int it = 0; it < 2; it++) {                                  \
                const int idx = tid + it * 256;                               \
                const int row = idx >> 2;                                     \
                const int p = idx & 3;                                        \
                const uint32_t d = OFF_B + row * 128 + SWZC(row, p * 16);     \
                CP16(bb_ + d, (const char*)(Bhi + (size_t)(n0 + row) * ldB    \
                                            + k0_ + p * 8));                  \
            }                                                                 \
        }                                                                     \
    } while (0)

    float acc[4][4][4];
#pragma unroll
    for (int i = 0; i < 4; i++)
#pragma unroll
        for (int j = 0; j < 4; j++)
#pragma unroll
            for (int r = 0; r < 4; r++) acc[i][j][r] = 0.f;

    LOAD_CHUNK(0, 0); CP_COMMIT();
    LOAD_CHUNK(1, 1); CP_COMMIT();

    // per-lane LDSM geometry
    const int aRow = lane & 15;                              // A: 16x16 frags
    const int aCol0 = lane & 16;                             // 0 / 16 bytes
    const int bRow0 = (lane & 7) + ((lane >> 4) & 1) * 8;    // B: 16-row pair
    const int bCol0 = ((lane >> 3) & 1) * 16;

    int stg = 0;                // stage holding chunk `ch`
    for (int ch = 0; ch < total; ch++) {
        CP_WAIT1();
        __syncthreads();

        const uint32_t bb = sb + stg * STG_B;

#pragma unroll
        for (int ks = 0; ks < 2; ks++) {
            const int colH = ks * 32;
            // --- fragment loads first (B frags + A tile 0) ---
            uint32_t bh[4][2], bl[4][2];
#pragma unroll
            for (int jj = 0; jj < 2; jj++) {
                const int row = wn + jj * 16 + bRow0;
                const uint32_t rb = bb + OFF_B + row * 128;
                LDSM4(&bh[jj * 2][0], rb + SWZC(row, colH + bCol0));
                if (TERMS == 3) LDSM4(&bl[jj * 2][0], rb + SWZC(row, colH + bCol0 + 64));
            }
            uint32_t ahc[4], alc[4], ahn[4], aln[4];
            {
                const int row = wm + aRow;
                const uint32_t ra = bb + row * 128;
                LDSM4(ahc, ra + SWZC(row, colH + aCol0));
                if (TERMS == 3) LDSM4(alc, ra + SWZC(row, colH + aCol0 + 64));
            }
            // --- overlap next chunk's cp.async issue with LDSM latency ---
            if (ks == 0) {
                int nstg = stg + 2; if (nstg >= NSTG) nstg -= NSTG;
                if (ch + 2 < total) { LOAD_CHUNK(ch + 2, nstg); }
                CP_COMMIT();
            }
            // --- MMAs, streaming A tiles one ahead ---
#pragma unroll
            for (int i = 0; i < 4; i++) {
                if (i < 3) {
                    const int row = wm + (i + 1) * 16 + aRow;
                    const uint32_t ra = bb + row * 128;
                    LDSM4(ahn, ra + SWZC(row, colH + aCol0));
                    if (TERMS == 3) LDSM4(aln, ra + SWZC(row, colH + aCol0 + 64));
                }
#pragma unroll
                for (int j = 0; j < 4; j++) {
                    MMA(acc[i][j], ahc, bh[j]);
                    if (TERMS == 3) {
                        MMA(acc[i][j], ahc, bl[j]);
                        MMA(acc[i][j], alc, bh[j]);
                    }
                }
#pragma unroll
                for (int r = 0; r < 4; r++) {
                    ahc[r] = ahn[r];
                    if (TERMS == 3) alc[r] = aln[r];
                }
            }
        }
        stg = stg + 1; if (stg >= NSTG) stg = 0;
    }
#undef LOAD_CHUNK

    // ---- epilogue ----
    const int cr = lane >> 2, cc = (lane & 3) * 2;
#pragma unroll
    for (int i = 0; i < 4; i++) {
        const int r0 = m0 + wm + i * 16 + cr;
#pragma unroll
        for (int j = 0; j < 4; j++) {
            const int col = n0 + wn + j * 8 + cc;
            const size_t o0 = (size_t)z * cBatch + (size_t)r0 * ldC + col;
            const size_t o1 = o0 + (size_t)8 * ldC;
            float v0 = acc[i][j][0] * alpha, v1 = acc[i][j][1] * alpha;
            float v2 = acc[i][j][2] * alpha, v3 = acc[i][j][3] * alpha;
            if (EPI == 0) {
                Cf[o0] = v0; Cf[o0 + 1] = v1;
                Cf[o1] = v2; Cf[o1 + 1] = v3;
            } else {
                __half h0 = __float2half_rn(v0), h1 = __float2half_rn(v1);
                __half h2 = __float2half_rn(v2), h3 = __float2half_rn(v3);
                Chi[o0] = h0; Chi[o0 + 1] = h1;
                Chi[o1] = h2; Chi[o1 + 1] = h3;
                Clo[o0] = __float2half_rn(v0 - __half2float(h0));
                Clo[o0 + 1] = __float2half_rn(v1 - __half2float(h1));
                Clo[o1] = __float2half_rn(v2 - __half2float(h2));
                Clo[o1 + 1] = __float2half_rn(v3 - __half2float(h3));
            }
        }
    }
}

// ---------------------------------------------------------------------------
// Split x -> xs (h/r, [B,N,D]) and xt (h only, [B,D,N])
// ---------------------------------------------------------------------------
__global__ __launch_bounds__(256) void split_x_kernel(const float* __restrict__ x) {
    __shared__ float t[32][33];
    const int b = blockIdx.z;
    const int d0 = blockIdx.x * 32, n0 = blockIdx.y * 32;
    const int tx = threadIdx.x & 31, ty = threadIdx.x >> 5;

    for (int i = ty; i < 32; i += 8)
        t[i][tx] = x[(size_t)b * N_ * D_ + (size_t)(n0 + i) * D_ + d0 + tx];
    __syncthreads();

    for (int i = ty; i < 32; i += 8) {
        float v = t[i][tx];
        __half h = __float2half_rn(v);
        size_t o = (size_t)b * N_ * D_ + (size_t)(n0 + i) * D_ + d0 + tx;
        g_xs_h[o] = h; g_xs_r[o] = __float2half_rn(v - __half2float(h));
    }
    for (int i = ty; i < 32; i += 8) {
        float v = t[tx][i];
        size_t o = (size_t)b * D_ * N_ + (size_t)(d0 + i) * N_ + n0 + tx;
        g_xt_h[o] = __float2half_rn(v);
    }
}

__global__ __launch_bounds__(256) void split_w_kernel(const float* __restrict__ W) {
    __shared__ float t[32][33];
    const int h = blockIdx.z;
    const int e0 = blockIdx.x * 32, d0 = blockIdx.y * 32;
    const int tx = threadIdx.x & 31, ty = threadIdx.x >> 5;

    for (int i = ty; i < 32; i += 8)
        t[i][tx] = W[(size_t)h * D_ * D_ + (size_t)(d0 + i) * D_ + e0 + tx];
    __syncthreads();

    for (int i = ty; i < 32; i += 8) {
        float v = t[tx][i];   // W[d0+tx][e0+i]
        __half hh = __float2half_rn(v);
        size_t o = (size_t)h * D_ * D_ + (size_t)(e0 + i) * D_ + d0 + tx;
        g_Wt_h[o] = hh; g_Wt_r[o] = __float2half_rn(v - __half2float(hh));
    }
}

// ---------------------------------------------------------------------------
// Softmax over rows of g_S; writes fp16 P (hi only)
// ---------------------------------------------------------------------------
__global__ __launch_bounds__(256) void softmax_split_kernel() {
    const size_t row = blockIdx.x;
    const float* p = g_S + row * N_;
    const int tid = threadIdx.x;
    __shared__ float red[8];

    float4 v = *(const float4*)&p[tid * 4];
    float m = fmaxf(fmaxf(v.x, v.y), fmaxf(v.z, v.w));
#pragma unroll
    for (int o = 16; o; o >>= 1) m = fmaxf(m, __shfl_xor_sync(0xFFFFFFFFu, m, o));
    if ((tid & 31) == 0) red[tid >> 5] = m;
    __syncthreads();
    float bm = red[0];
#pragma unroll
    for (int i = 1; i < 8; i++) bm = fmaxf(bm, red[i]);
    __syncthreads();

    v.x = __expf(v.x - bm); v.y = __expf(v.y - bm);
    v.z = __expf(v.z - bm); v.w = __expf(v.w - bm);
    float s = v.x + v.y + v.z + v.w;
#pragma unroll
    for (int o = 16; o; o >>= 1) s += __shfl_xor_sync(0xFFFFFFFFu, s, o);
    if ((tid & 31) == 0) red[tid >> 5] = s;
    __syncthreads();
    float bs = 0.f;
#pragma unroll
    for (int i = 0; i < 8; i++) bs += red[i];
    float inv = 1.0f / bs;

    __half2* dst = (__half2*)&g_P_h[row * N_ + tid * 4];
    dst[0] = __floats2half2_rn(v.x * inv, v.y * inv);
    dst[1] = __floats2half2_rn(v.z * inv, v.w * inv);
}

// ---------------------------------------------------------------------------
// out[b,n,d] = 0.25 * sum_h scratch[b*4+h, n, d]
// ---------------------------------------------------------------------------
__global__ __launch_bounds__(256) void reduce_heads_kernel(float* __restrict__ out) {
    const size_t i4 = ((size_t)blockIdx.x * 256 + threadIdx.x) * 4;
    const size_t b = i4 / ((size_t)N_ * D_);
    const size_t w = i4 % ((size_t)N_ * D_);
    const float* s = g_S + (b * 4) * (size_t)N_ * D_ + w;
    float4 v0 = *(const float4*)(s);
    float4 v1 = *(const float4*)(s + (size_t)N_ * D_);
    float4 v2 = *(const float4*)(s + 2 * (size_t)N_ * D_);
    float4 v3 = *(const float4*)(s + 3 * (size_t)N_ * D_);
    float4 r;
    r.x = 0.25f * (v0.x + v1.x + v2.x + v3.x);
    r.y = 0.25f * (v0.y + v1.y + v2.y + v3.y);
    r.z = 0.25f * (v0.z + v1.z + v2.z + v3.z);
    r.w = 0.25f * (v0.w + v1.w + v2.w + v3.w);
    *(float4*)&out[i4] = r;
}

// ---------------------------------------------------------------------------
extern "C" void kernel_launch(void* const* d_in, const int* in_sizes, int n_in,
                              void* d_out, int out_size) {
    const float* x = (const float*)d_in[0];   // [8,1024,512]
    const float* W = (const float*)d_in[1];   // [4,512,512]
    float* out = (float*)d_out;               // [8,1024,512]

    cudaFuncSetAttribute(gemm_mma<0, 3>, cudaFuncAttributeMaxDynamicSharedMemorySize, GSMEM);
    cudaFuncSetAttribute(gemm_mma<1, 3>, cudaFuncAttributeMaxDynamicSharedMemorySize, GSMEM);
    cudaFuncSetAttribute(gemm_mma<0, 1>, cudaFuncAttributeMaxDynamicSharedMemorySize, GSMEM);

    __half *xs_h, *xs_r, *xt_h, *Wt_h, *Wt_r, *Y_h, *Y_r, *P_h;
    float* Sf;
    cudaGetSymbolAddress((void**)&xs_h, g_xs_h);
    cudaGetSymbolAddress((void**)&xs_r, g_xs_r);
    cudaGetSymbolAddress((void**)&xt_h, g_xt_h);
    cudaGetSymbolAddress((void**)&Wt_h, g_Wt_h);
    cudaGetSymbolAddress((void**)&Wt_r, g_Wt_r);
    cudaGetSymbolAddress((void**)&Y_h, g_Y_h);
    cudaGetSymbolAddress((void**)&Y_r, g_Y_r);
    cudaGetSymbolAddress((void**)&P_h, g_P_h);
    cudaGetSymbolAddress((void**)&Sf, g_S);

    const float SCALE = 0.04419417382415922f;   // 512^-0.5

    split_x_kernel<<<dim3(D_ / 32, N_ / 32, B_), 256>>>(x);
    split_w_kernel<<<dim3(D_ / 32, D_ / 32, H_), 256>>>(W);

    // K1: Y[b,h] = xs[b] @ Wt[h]^T  (3-term) -> fp16 h/r Y
    gemm_mma<1, 3><<<dim3(D_ / 128, N_ / 128, B_ * H_), 256, GSMEM>>>(
        xs_h, xs_r, D_, (size_t)N_ * D_, 4, 8,
        Wt_h, Wt_r, D_, (size_t)D_ * D_, 1, 4,
        D_,
        nullptr, Y_h, Y_r, D_, (size_t)N_ * D_, 1.0f);

    // K2: S[b,h] = scale * Y[b,h] @ xs[b]^T  (3-term) -> fp32
    gemm_mma<0, 3><<<dim3(N_ / 128, N_ / 128, B_ * H_), 256, GSMEM>>>(
        Y_h, Y_r, D_, (size_t)N_ * D_, 1, 32,
        xs_h, xs_r, D_, (size_t)N_ * D_, 4, 8,
        D_,
        Sf, nullptr, nullptr, N_, (size_t)N_ * N_, SCALE);

    softmax_split_kernel<<<B_ * H_ * N_, 256>>>();

    // K4: scratch[b,h] = P_h[b,h] @ xt_h[b]^T  (1-term fp16) -> fp32 scratch
    gemm_mma<0, 1><<<dim3(D_ / 128, N_ / 128, B_ * H_), 256, GSMEM>>>(
        P_h, nullptr, N_, (size_t)N_ * N_, 1, 32,
        xt_h, nullptr, N_, (size_t)D_ * N_, 4, 8,
        N_,
        Sf, nullptr, nullptr, D_, (size_t)N_ * D_, 1.0f);

    // out = 0.25 * sum_h scratch
    reduce_heads_kernel<<<(B_ * N_ * D_) / (4 * 256), 256>>>(out);
}

// round 11
// speedup vs baseline: 4.2094x; 1.0173x over previous
#include <cuda_runtime.h>
#include <cuda_fp16.h>
#include <cstdint>
#include <math.h>

#define B_ 8
#define N_ 1024
#define D_ 512
#define H_ 4

// ---------------------------------------------------------------------------
// Scratch (device globals; no allocation allowed)
// ---------------------------------------------------------------------------
__device__ __align__(16) __half g_xs_h[(size_t)B_ * N_ * D_];
__device__ __align__(16) __half g_xs_r[(size_t)B_ * N_ * D_];
__device__ __align__(16) __half g_xt_h[(size_t)B_ * D_ * N_];
__device__ __align__(16) __half g_Wt_h[(size_t)H_ * D_ * D_];
__device__ __align__(16) __half g_Wt_r[(size_t)H_ * D_ * D_];
__device__ __align__(16) __half g_Y_h[(size_t)B_ * H_ * N_ * D_];
__device__ __align__(16) __half g_Y_r[(size_t)B_ * H_ * N_ * D_];
__device__ __align__(16) float  g_S  [(size_t)B_ * H_ * N_ * N_];  // also K4 scratch
__device__ __align__(16) __half g_P_h[(size_t)B_ * H_ * N_ * N_];

// ---------------------------------------------------------------------------
// helpers (portable sm_80+ PTX)
// ---------------------------------------------------------------------------
__device__ __forceinline__ uint32_t smem_u32(const void* p) {
    uint32_t a;
    asm("{ .reg .u64 t; cvta.to.shared.u64 t, %1; cvt.u32.u64 %0, t; }"
        : "=r"(a) : "l"(p));
    return a;
}

#define CP16(dst, src) \
    asm volatile("cp.async.cg.shared.global [%0], [%1], 16;" \
                 :: "r"(dst), "l"(src))
#define CP_COMMIT() asm volatile("cp.async.commit_group;" ::: "memory")
#define CP_WAIT1()  asm volatile("cp.async.wait_group 1;"  ::: "memory")

#define LDSM4(r, a)                                                           \
    asm volatile("ldmatrix.sync.aligned.m8n8.x4.shared.b16 {%0,%1,%2,%3}, [%4];" \
                 : "=r"((r)[0]), "=r"((r)[1]), "=r"((r)[2]), "=r"((r)[3])     \
                 : "r"(a))

#define MMA(c, a, b)                                                          \
    asm volatile("mma.sync.aligned.m16n8k16.row.col.f32.f16.f16.f32 "         \
                 "{%0,%1,%2,%3},{%4,%5,%6,%7},{%8,%9},{%0,%1,%2,%3};"         \
                 : "+f"((c)[0]), "+f"((c)[1]), "+f"((c)[2]), "+f"((c)[3])     \
                 : "r"((a)[0]), "r"((a)[1]), "r"((a)[2]), "r"((a)[3]),        \
                   "r"((b)[0]), "r"((b)[1]))

// swizzle within a 128B row
#define SWZC(row, colB) ((uint32_t)(colB) ^ (((uint32_t)(row) & 7u) << 4))

// smem stages: 32KB each, 3 stages.
// TERMS=3: K-chunk 32, row = [hi k0..31 | lo k0..31] (128B)
// TERMS=1: K-chunk 64, row = [hi k0..63] (128B)
#define AT_B   (128 * 128)           // 16384
#define BT_B   (128 * 128)           // 16384
#define STG_B  (AT_B + BT_B)         // 32768
#define OFF_B  AT_B
#define NSTG   3
#define GSMEM  (NSTG * STG_B)        // 98304

// ---------------------------------------------------------------------------
// Split-fp16 mma.sync GEMM (NT): C[m,n] = alpha * sum_k A[m,k]B[n,k]
// TERMS 3: ah*bh + ah*bl + al*bh  (A = Ah+Ar, B = Bh+Br)
// TERMS 1: ah*bh                  (pure fp16)
// CTA tile 128x128, 8 warps (2m x 4n), warp tile 64x32,
// 3-stage cp.async ring, 2 CTAs/SM.
// MMA ordering is term-major so same-acc dependent MMAs are 4 apart.
// EPI 0: fp32 C.  EPI 1: (h, r) fp16 pair.
// ---------------------------------------------------------------------------
template <int EPI, int TERMS>
__global__ __launch_bounds__(256, 2) void gemm_mma(
    const __half* __restrict__ Ahi, const __half* __restrict__ Alo,
    int ldA, size_t aBatch, int aDiv, int aMod,
    const __half* __restrict__ Bhi, const __half* __restrict__ Blo,
    int ldB, size_t bBatch, int bDiv, int bMod,
    int K,
    float* __restrict__ Cf,
    __half* __restrict__ Chi, __half* __restrict__ Clo,
    int ldC, size_t cBatch, float alpha)
{
    extern __shared__ char smem[];
    const uint32_t sb = smem_u32(smem);
    const int tid = threadIdx.x;
    const int wid = tid >> 5, lane = tid & 31;
    const int wm = (wid >> 2) * 64;     // 2 m-groups
    const int wn = (wid & 3) * 32;      // 4 n-groups
    const int z = blockIdx.z;
    const int m0 = blockIdx.y * 128;
    const int n0 = blockIdx.x * 128;

    Ahi += (size_t)((z / aDiv) % aMod) * aBatch;
    if (TERMS == 3) Alo += (size_t)((z / aDiv) % aMod) * aBatch;
    Bhi += (size_t)((z / bDiv) % bMod) * bBatch;
    if (TERMS == 3) Blo += (size_t)((z / bDiv) % bMod) * bBatch;

    constexpr int KC  = (TERMS == 3) ? 32 : 64;   // K per chunk
    constexpr int NKS = KC / 16;                  // k16 steps per chunk
    const int total = K / KC;

#define LOAD_CHUNK(ch, stg) do {                                              \
        const int k0_ = (ch) * KC;                                            \
        const uint32_t bb_ = sb + (stg) * STG_B;                              \
        if (TERMS == 3) {                                                     \
            _Pragma("unroll")                                                 \
            for (int it = 0; it < 4; it++) {   /* A: 128 rows x 8 pieces */   \
                const int idx = tid + it * 256;                               \
                const int row = idx >> 3;                                     \
                const int p = idx & 7;                                        \
                const __half* src = (p < 4) ? Ahi : Alo;                      \
                const uint32_t d = row * 128 + SWZC(row, p * 16);             \
                CP16(bb_ + d, (const char*)(src + (size_t)(m0 + row) * ldA    \
                                            + k0_ + (p & 3) * 8));            \
            }                                                                 \
            _Pragma("unroll")                                                 \
            for (int it = 0; it < 4; it++) {  /* B: 128 rows x 8 pieces */    \
                const int idx = tid + it * 256;                               \
                const int row = idx >> 3;                                     \
                const int p = idx & 7;                                        \
                const __half* src = (p < 4) ? Bhi : Blo;                      \
                const uint32_t d = OFF_B + row * 128 + SWZC(row, p * 16);     \
                CP16(bb_ + d, (const char*)(src + (size_t)(n0 + row) * ldB    \
                                            + k0_ + (p & 3) * 8));            \
            }                                                                 \
        } else {            /* hi only, 64 k per row: 128 rows x 8 pieces */  \
            _Pragma("unroll")                                                 \
            for (int it = 0; it < 4; it++) {                                  \
                const int idx = tid + it * 256;                               \
                const int row = idx >> 3;                                     \
                const int p = idx & 7;                                        \
                const uint32_t d = row * 128 + SWZC(row, p * 16);             \
                CP16(bb_ + d, (const char*)(Ahi + (size_t)(m0 + row) * ldA    \
                                            + k0_ + p * 8));                  \
            }                                                                 \
            _Pragma("unroll")                                                 \
            for (int it = 0; it < 4; it++) {                                  \
                const int idx = tid + it * 256;                               \
                const int row = idx >> 3;                                     \
                const int p = idx & 7;                                        \
                const uint32_t d = OFF_B + row * 128 + SWZC(row, p * 16);     \
                CP16(bb_ + d, (const char*)(Bhi + (size_t)(n0 + row) * ldB    \
                                            + k0_ + p * 8));                  \
            }                                                                 \
        }                                                                     \
    } while (0)

    float acc[4][4][4];
#pragma unroll
    for (int i = 0; i < 4; i++)
#pragma unroll
        for (int j = 0; j < 4; j++)
#pragma unroll
            for (int r = 0; r < 4; r++) acc[i][j][r] = 0.f;

    LOAD_CHUNK(0, 0); CP_COMMIT();
    LOAD_CHUNK(1, 1); CP_COMMIT();

    // per-lane LDSM geometry
    const int aRow = lane & 15;                              // A: 16x16 frags
    const int aCol0 = lane & 16;                             // 0 / 16 bytes
    const int bRow0 = (lane & 7) + ((lane >> 4) & 1) * 8;    // B: 16-row pair
    const int bCol0 = ((lane >> 3) & 1) * 16;

    int stg = 0;                // stage holding chunk `ch`
    for (int ch = 0; ch < total; ch++) {
        CP_WAIT1();
        __syncthreads();

        const uint32_t bb = sb + stg * STG_B;

#pragma unroll
        for (int ks = 0; ks < NKS; ks++) {
            const int colH = ks * 32;
            // --- fragment loads first (B frags + A tile 0) ---
            uint32_t bh[4][2], bl[4][2];
#pragma unroll
            for (int jj = 0; jj < 2; jj++) {
                const int row = wn + jj * 16 + bRow0;
                const uint32_t rb = bb + OFF_B + row * 128;
                LDSM4(&bh[jj * 2][0], rb + SWZC(row, colH + bCol0));
                if (TERMS == 3) LDSM4(&bl[jj * 2][0], rb + SWZC(row, colH + bCol0 + 64));
            }
            uint32_t ahc[4], alc[4], ahn[4], aln[4];
            {
                const int row = wm + aRow;
                const uint32_t ra = bb + row * 128;
                LDSM4(ahc, ra + SWZC(row, colH + aCol0));
                if (TERMS == 3) LDSM4(alc, ra + SWZC(row, colH + aCol0 + 64));
            }
            // --- overlap next chunk's cp.async issue with LDSM latency ---
            if (ks == 0) {
                int nstg = stg + 2; if (nstg >= NSTG) nstg -= NSTG;
                if (ch + 2 < total) { LOAD_CHUNK(ch + 2, nstg); }
                CP_COMMIT();
            }
            // --- MMAs: term-major so same-acc dependents are 4 apart ---
#pragma unroll
            for (int i = 0; i < 4; i++) {
                if (i < 3) {
                    const int row = wm + (i + 1) * 16 + aRow;
                    const uint32_t ra = bb + row * 128;
                    LDSM4(ahn, ra + SWZC(row, colH + aCol0));
                    if (TERMS == 3) LDSM4(aln, ra + SWZC(row, colH + aCol0 + 64));
                }
#pragma unroll
                for (int j = 0; j < 4; j++) MMA(acc[i][j], ahc, bh[j]);
                if (TERMS == 3) {
#pragma unroll
                    for (int j = 0; j < 4; j++) MMA(acc[i][j], ahc, bl[j]);
#pragma unroll
                    for (int j = 0; j < 4; j++) MMA(acc[i][j], alc, bh[j]);
                }
#pragma unroll
                for (int r = 0; r < 4; r++) {
                    ahc[r] = ahn[r];
                    if (TERMS == 3) alc[r] = aln[r];
                }
            }
        }
        stg = stg + 1; if (stg >= NSTG) stg = 0;
    }
#undef LOAD_CHUNK

    // ---- epilogue ----
    const int cr = lane >> 2, cc = (lane & 3) * 2;
#pragma unroll
    for (int i = 0; i < 4; i++) {
        const int r0 = m0 + wm + i * 16 + cr;
#pragma unroll
        for (int j = 0; j < 4; j++) {
            const int col = n0 + wn + j * 8 + cc;
            const size_t o0 = (size_t)z * cBatch + (size_t)r0 * ldC + col;
            const size_t o1 = o0 + (size_t)8 * ldC;
            float v0 = acc[i][j][0] * alpha, v1 = acc[i][j][1] * alpha;
            float v2 = acc[i][j][2] * alpha, v3 = acc[i][j][3] * alpha;
            if (EPI == 0) {
                Cf[o0] = v0; Cf[o0 + 1] = v1;
                Cf[o1] = v2; Cf[o1 + 1] = v3;
            } else {
                __half h0 = __float2half_rn(v0), h1 = __float2half_rn(v1);
                __half h2 = __float2half_rn(v2), h3 = __float2half_rn(v3);
                Chi[o0] = h0; Chi[o0 + 1] = h1;
                Chi[o1] = h2; Chi[o1 + 1] = h3;
                Clo[o0] = __float2half_rn(v0 - __half2float(h0));
                Clo[o0 + 1] = __float2half_rn(v1 - __half2float(h1));
                Clo[o1] = __float2half_rn(v2 - __half2float(h2));
                Clo[o1 + 1] = __float2half_rn(v3 - __half2float(h3));
            }
        }
    }
}

// ---------------------------------------------------------------------------
// Split x -> xs (h/r, [B,N,D]) and xt (h only, [B,D,N])
// ---------------------------------------------------------------------------
__global__ __launch_bounds__(256) void split_x_kernel(const float* __restrict__ x) {
    __shared__ float t[32][33];
    const int b = blockIdx.z;
    const int d0 = blockIdx.x * 32, n0 = blockIdx.y * 32;
    const int tx = threadIdx.x & 31, ty = threadIdx.x >> 5;

    for (int i = ty; i < 32; i += 8)
        t[i][tx] = x[(size_t)b * N_ * D_ + (size_t)(n0 + i) * D_ + d0 + tx];
    __syncthreads();

    for (int i = ty; i < 32; i += 8) {
        float v = t[i][tx];
        __half h = __float2half_rn(v);
        size_t o = (size_t)b * N_ * D_ + (size_t)(n0 + i) * D_ + d0 + tx;
        g_xs_h[o] = h; g_xs_r[o] = __float2half_rn(v - __half2float(h));
    }
    for (int i = ty; i < 32; i += 8) {
        float v = t[tx][i];
        size_t o = (size_t)b * D_ * N_ + (size_t)(d0 + i) * N_ + n0 + tx;
        g_xt_h[o] = __float2half_rn(v);
    }
}

__global__ __launch_bounds__(256) void split_w_kernel(const float* __restrict__ W) {
    __shared__ float t[32][33];
    const int h = blockIdx.z;
    const int e0 = blockIdx.x * 32, d0 = blockIdx.y * 32;
    const int tx = threadIdx.x & 31, ty = threadIdx.x >> 5;

    for (int i = ty; i < 32; i += 8)
        t[i][tx] = W[(size_t)h * D_ * D_ + (size_t)(d0 + i) * D_ + e0 + tx];
    __syncthreads();

    for (int i = ty; i < 32; i += 8) {
        float v = t[tx][i];   // W[d0+tx][e0+i]
        __half hh = __float2half_rn(v);
        size_t o = (size_t)h * D_ * D_ + (size_t)(e0 + i) * D_ + d0 + tx;
        g_Wt_h[o] = hh; g_Wt_r[o] = __float2half_rn(v - __half2float(hh));
    }
}

// ---------------------------------------------------------------------------
// Softmax over rows of g_S; writes fp16 P (hi only)
// ---------------------------------------------------------------------------
__global__ __launch_bounds__(256) void softmax_split_kernel() {
    const size_t row = blockIdx.x;
    const float* p = g_S + row * N_;
    const int tid = threadIdx.x;
    __shared__ float red[8];

    float4 v = *(const float4*)&p[tid * 4];
    float m = fmaxf(fmaxf(v.x, v.y), fmaxf(v.z, v.w));
#pragma unroll
    for (int o = 16; o; o >>= 1) m = fmaxf(m, __shfl_xor_sync(0xFFFFFFFFu, m, o));
    if ((tid & 31) == 0) red[tid >> 5] = m;
    __syncthreads();
    float bm = red[0];
#pragma unroll
    for (int i = 1; i < 8; i++) bm = fmaxf(bm, red[i]);
    __syncthreads();

    v.x = __expf(v.x - bm); v.y = __expf(v.y - bm);
    v.z = __expf(v.z - bm); v.w = __expf(v.w - bm);
    float s = v.x + v.y + v.z + v.w;
#pragma unroll
    for (int o = 16; o; o >>= 1) s += __shfl_xor_sync(0xFFFFFFFFu, s, o);
    if ((tid & 31) == 0) red[tid >> 5] = s;
    __syncthreads();
    float bs = 0.f;
#pragma unroll
    for (int i = 0; i < 8; i++) bs += red[i];
    float inv = 1.0f / bs;

    __half2* dst = (__half2*)&g_P_h[row * N_ + tid * 4];
    dst[0] = __floats2half2_rn(v.x * inv, v.y * inv);
    dst[1] = __floats2half2_rn(v.z * inv, v.w * inv);
}

// ---------------------------------------------------------------------------
// out[b,n,d] = 0.25 * sum_h scratch[b*4+h, n, d]
// ---------------------------------------------------------------------------
__global__ __launch_bounds__(256) void reduce_heads_kernel(float* __restrict__ out) {
    const size_t i4 = ((size_t)blockIdx.x * 256 + threadIdx.x) * 4;
    const size_t b = i4 / ((size_t)N_ * D_);
    const size_t w = i4 % ((size_t)N_ * D_);
    const float* s = g_S + (b * 4) * (size_t)N_ * D_ + w;
    float4 v0 = *(const float4*)(s);
    float4 v1 = *(const float4*)(s + (size_t)N_ * D_);
    float4 v2 = *(const float4*)(s + 2 * (size_t)N_ * D_);
    float4 v3 = *(const float4*)(s + 3 * (size_t)N_ * D_);
    float4 r;
    r.x = 0.25f * (v0.x + v1.x + v2.x + v3.x);
    r.y = 0.25f * (v0.y + v1.y + v2.y + v3.y);
    r.z = 0.25f * (v0.z + v1.z + v2.z + v3.z);
    r.w = 0.25f * (v0.w + v1.w + v2.w + v3.w);
    *(float4*)&out[i4] = r;
}

// ---------------------------------------------------------------------------
extern "C" void kernel_launch(void* const* d_in, const int* in_sizes, int n_in,
                              void* d_out, int out_size) {
    const float* x = (const float*)d_in[0];   // [8,1024,512]
    const float* W = (const float*)d_in[1];   // [4,512,512]
    float* out = (float*)d_out;               // [8,1024,512]

    cudaFuncSetAttribute(gemm_mma<0, 3>, cudaFuncAttributeMaxDynamicSharedMemorySize, GSMEM);
    cudaFuncSetAttribute(gemm_mma<1, 3>, cudaFuncAttributeMaxDynamicSharedMemorySize, GSMEM);
    cudaFuncSetAttribute(gemm_mma<0, 1>, cudaFuncAttributeMaxDynamicSharedMemorySize, GSMEM);

    __half *xs_h, *xs_r, *xt_h, *Wt_h, *Wt_r, *Y_h, *Y_r, *P_h;
    float* Sf;
    cudaGetSymbolAddress((void**)&xs_h, g_xs_h);
    cudaGetSymbolAddress((void**)&xs_r, g_xs_r);
    cudaGetSymbolAddress((void**)&xt_h, g_xt_h);
    cudaGetSymbolAddress((void**)&Wt_h, g_Wt_h);
    cudaGetSymbolAddress((void**)&Wt_r, g_Wt_r);
    cudaGetSymbolAddress((void**)&Y_h, g_Y_h);
    cudaGetSymbolAddress((void**)&Y_r, g_Y_r);
    cudaGetSymbolAddress((void**)&P_h, g_P_h);
    cudaGetSymbolAddress((void**)&Sf, g_S);

    const float SCALE = 0.04419417382415922f;   // 512^-0.5

    split_x_kernel<<<dim3(D_ / 32, N_ / 32, B_), 256>>>(x);
    split_w_kernel<<<dim3(D_ / 32, D_ / 32, H_), 256>>>(W);

    // K1: Y[b,h] = xs[b] @ Wt[h]^T  (3-term) -> fp16 h/r Y
    gemm_mma<1, 3><<<dim3(D_ / 128, N_ / 128, B_ * H_), 256, GSMEM>>>(
        xs_h, xs_r, D_, (size_t)N_ * D_, 4, 8,
        Wt_h, Wt_r, D_, (size_t)D_ * D_, 1, 4,
        D_,
        nullptr, Y_h, Y_r, D_, (size_t)N_ * D_, 1.0f);

    // K2: S[b,h] = scale * Y[b,h] @ xs[b]^T  (3-term) -> fp32
    gemm_mma<0, 3><<<dim3(N_ / 128, N_ / 128, B_ * H_), 256, GSMEM>>>(
        Y_h, Y_r, D_, (size_t)N_ * D_, 1, 32,
        xs_h, xs_r, D_, (size_t)N_ * D_, 4, 8,
        D_,
        Sf, nullptr, nullptr, N_, (size_t)N_ * N_, SCALE);

    softmax_split_kernel<<<B_ * H_ * N_, 256>>>();

    // K4: scratch[b,h] = P_h[b,h] @ xt_h[b]^T  (1-term fp16, K-chunk 64)
    gemm_mma<0, 1><<<dim3(D_ / 128, N_ / 128, B_ * H_), 256, GSMEM>>>(
        P_h, nullptr, N_, (size_t)N_ * N_, 1, 32,
        xt_h, nullptr, N_, (size_t)D_ * N_, 4, 8,
        N_,
        Sf, nullptr, nullptr, D_, (size_t)N_ * D_, 1.0f);

    // out = 0.25 * sum_h scratch
    reduce_heads_kernel<<<(B_ * N_ * D_) / (4 * 256), 256>>>(out);
}

// round 12
// speedup vs baseline: 4.5065x; 1.0706x over previous
#include <cuda_runtime.h>
#include <cuda_fp16.h>
#include <cstdint>
#include <math.h>

#define B_ 8
#define N_ 1024
#define D_ 512
#define H_ 4

// ---------------------------------------------------------------------------
// Scratch (device globals; no allocation allowed)
// ---------------------------------------------------------------------------
__device__ __align__(16) __half g_xs_h[(size_t)B_ * N_ * D_];
__device__ __align__(16) __half g_xs_r[(size_t)B_ * N_ * D_];
__device__ __align__(16) __half g_xt_h[(size_t)B_ * D_ * N_];
__device__ __align__(16) __half g_Wt_h[(size_t)H_ * D_ * D_];
__device__ __align__(16) __half g_Wt_r[(size_t)H_ * D_ * D_];
__device__ __align__(16) __half g_Y_h[(size_t)B_ * H_ * N_ * D_];
__device__ __align__(16) __half g_Y_r[(size_t)B_ * H_ * N_ * D_];
__device__ __align__(16) float  g_S  [(size_t)B_ * H_ * N_ * N_];
__device__ __align__(16) __half g_P_h[(size_t)B_ * H_ * N_ * N_];

// ---------------------------------------------------------------------------
// helpers (portable sm_80+ PTX)
// ---------------------------------------------------------------------------
__device__ __forceinline__ uint32_t smem_u32(const void* p) {
    uint32_t a;
    asm("{ .reg .u64 t; cvta.to.shared.u64 t, %1; cvt.u32.u64 %0, t; }"
        : "=r"(a) : "l"(p));
    return a;
}

#define CP16(dst, src) \
    asm volatile("cp.async.cg.shared.global [%0], [%1], 16;" \
                 :: "r"(dst), "l"(src))
#define CP_COMMIT() asm volatile("cp.async.commit_group;" ::: "memory")
#define CP_WAIT1()  asm volatile("cp.async.wait_group 1;"  ::: "memory")

#define LDSM4(r, a)                                                           \
    asm volatile("ldmatrix.sync.aligned.m8n8.x4.shared.b16 {%0,%1,%2,%3}, [%4];" \
                 : "=r"((r)[0]), "=r"((r)[1]), "=r"((r)[2]), "=r"((r)[3])     \
                 : "r"(a))

#define MMA(c, a, b)                                                          \
    asm volatile("mma.sync.aligned.m16n8k16.row.col.f32.f16.f16.f32 "         \
                 "{%0,%1,%2,%3},{%4,%5,%6,%7},{%8,%9},{%0,%1,%2,%3};"         \
                 : "+f"((c)[0]), "+f"((c)[1]), "+f"((c)[2]), "+f"((c)[3])     \
                 : "r"((a)[0]), "r"((a)[1]), "r"((a)[2]), "r"((a)[3]),        \
                   "r"((b)[0]), "r"((b)[1]))

// swizzle within a 128B row
#define SWZC(row, colB) ((uint32_t)(colB) ^ (((uint32_t)(row) & 7u) << 4))

// smem stages: 32KB each, 3 stages.
// TERMS=3: K-chunk 32, row = [hi k0..31 | lo k0..31] (128B)
// TERMS=1: K-chunk 64, row = [hi k0..63] (128B)
#define AT_B   (128 * 128)           // 16384
#define BT_B   (128 * 128)           // 16384
#define STG_B  (AT_B + BT_B)         // 32768
#define OFF_B  AT_B
#define NSTG   3
#define GSMEM  (NSTG * STG_B)        // 98304

// ---------------------------------------------------------------------------
// Split-fp16 mma.sync GEMM (NT):
//   C[m,n] = alpha * sum_seg sum_k A_seg[m,k] B[n,k]
// TERMS 3: ah*bh + ah*bl + al*bh  (A = Ah+Ar, B = Bh+Br)
// TERMS 1: ah*bh                  (pure fp16)
// CTA tile 128x128, 8 warps (2m x 4n), warp tile 64x32,
// 3-stage cp.async ring, 2 CTAs/SM.
// EPI 0: fp32 C.  EPI 1: (h, r) fp16 pair.
// ---------------------------------------------------------------------------
template <int EPI, int TERMS>
__global__ __launch_bounds__(256, 2) void gemm_mma(
    const __half* __restrict__ Ahi, const __half* __restrict__ Alo,
    int ldA, size_t aBatch, int aDiv, int aMod, size_t aSeg, int nSeg,
    const __half* __restrict__ Bhi, const __half* __restrict__ Blo,
    int ldB, size_t bBatch, int bDiv, int bMod,
    int K,
    float* __restrict__ Cf,
    __half* __restrict__ Chi, __half* __restrict__ Clo,
    int ldC, size_t cBatch, float alpha)
{
    extern __shared__ char smem[];
    const uint32_t sb = smem_u32(smem);
    const int tid = threadIdx.x;
    const int wid = tid >> 5, lane = tid & 31;
    const int wm = (wid >> 2) * 64;     // 2 m-groups
    const int wn = (wid & 3) * 32;      // 4 n-groups
    const int z = blockIdx.z;
    const int m0 = blockIdx.y * 128;
    const int n0 = blockIdx.x * 128;

    Ahi += (size_t)((z / aDiv) % aMod) * aBatch;
    if (TERMS == 3) Alo += (size_t)((z / aDiv) % aMod) * aBatch;
    Bhi += (size_t)((z / bDiv) % bMod) * bBatch;
    if (TERMS == 3) Blo += (size_t)((z / bDiv) % bMod) * bBatch;

    constexpr int KC  = (TERMS == 3) ? 32 : 64;   // K per chunk
    constexpr int NKS = KC / 16;                  // k16 steps per chunk
    const int cps = K / KC;                       // chunks per segment
    const int total = nSeg * cps;

#define LOAD_CHUNK(ch, stg) do {                                              \
        const int seg_ = (ch) / cps;                                          \
        const int k0_ = ((ch) % cps) * KC;                                    \
        const uint32_t bb_ = sb + (stg) * STG_B;                              \
        const __half* Ah_ = Ahi + (size_t)seg_ * aSeg;                        \
        if (TERMS == 3) {                                                     \
            const __half* Al_ = Alo + (size_t)seg_ * aSeg;                    \
            _Pragma("unroll")                                                 \
            for (int it = 0; it < 4; it++) {   /* A: 128 rows x 8 pieces */   \
                const int idx = tid + it * 256;                               \
                const int row = idx >> 3;                                     \
                const int p = idx & 7;                                        \
                const __half* src = (p < 4) ? Ah_ : Al_;                      \
                const uint32_t d = row * 128 + SWZC(row, p * 16);             \
                CP16(bb_ + d, (const char*)(src + (size_t)(m0 + row) * ldA    \
                                            + k0_ + (p & 3) * 8));            \
            }                                                                 \
            _Pragma("unroll")                                                 \
            for (int it = 0; it < 4; it++) {  /* B: 128 rows x 8 pieces */    \
                const int idx = tid + it * 256;                               \
                const int row = idx >> 3;                                     \
                const int p = idx & 7;                                        \
                const __half* src = (p < 4) ? Bhi : Blo;                      \
                const uint32_t d = OFF_B + row * 128 + SWZC(row, p * 16);     \
                CP16(bb_ + d, (const char*)(src + (size_t)(n0 + row) * ldB    \
                                            + k0_ + (p & 3) * 8));            \
            }                                                                 \
        } else {            /* hi only, 64 k per row: 128 rows x 8 pieces */  \
            _Pragma("unroll")                                                 \
            for (int it = 0; it < 4; it++) {                                  \
                const int idx = tid + it * 256;                               \
                const int row = idx >> 3;                                     \
                const int p = idx & 7;                                        \
                const uint32_t d = row * 128 + SWZC(row, p * 16);             \
                CP16(bb_ + d, (const char*)(Ah_ + (size_t)(m0 + row) * ldA    \
                                            + k0_ + p * 8));                  \
            }                                                                 \
            _Pragma("unroll")                                                 \
            for (int it = 0; it < 4; it++) {                                  \
                const int idx = tid + it * 256;                               \
                const int row = idx >> 3;                                     \
                const int p = idx & 7;                                        \
                const uint32_t d = OFF_B + row * 128 + SWZC(row, p * 16);     \
                CP16(bb_ + d, (const char*)(Bhi + (size_t)(n0 + row) * ldB    \
                                            + k0_ + p * 8));                  \
            }                                                                 \
        }                                                                     \
    } while (0)

    float acc[4][4][4];
#pragma unroll
    for (int i = 0; i < 4; i++)
#pragma unroll
        for (int j = 0; j < 4; j++)
#pragma unroll
            for (int r = 0; r < 4; r++) acc[i][j][r] = 0.f;

    LOAD_CHUNK(0, 0); CP_COMMIT();
    LOAD_CHUNK(1, 1); CP_COMMIT();

    // per-lane LDSM geometry
    const int aRow = lane & 15;                              // A: 16x16 frags
    const int aCol0 = lane & 16;                             // 0 / 16 bytes
    const int bRow0 = (lane & 7) + ((lane >> 4) & 1) * 8;    // B: 16-row pair
    const int bCol0 = ((lane >> 3) & 1) * 16;

    int stg = 0;                // stage holding chunk `ch`
    for (int ch = 0; ch < total; ch++) {
        CP_WAIT1();
        __syncthreads();

        const uint32_t bb = sb + stg * STG_B;

#pragma unroll
        for (int ks = 0; ks < NKS; ks++) {
            const int colH = ks * 32;
            // --- fragment loads first (B frags + A tile 0) ---
            uint32_t bh[4][2], bl[4][2];
#pragma unroll
            for (int jj = 0; jj < 2; jj++) {
                const int row = wn + jj * 16 + bRow0;
                const uint32_t rb = bb + OFF_B + row * 128;
                LDSM4(&bh[jj * 2][0], rb + SWZC(row, colH + bCol0));
                if (TERMS == 3) LDSM4(&bl[jj * 2][0], rb + SWZC(row, colH + bCol0 + 64));
            }
            uint32_t ahc[4], alc[4], ahn[4], aln[4];
            {
                const int row = wm + aRow;
                const uint32_t ra = bb + row * 128;
                LDSM4(ahc, ra + SWZC(row, colH + aCol0));
                if (TERMS == 3) LDSM4(alc, ra + SWZC(row, colH + aCol0 + 64));
            }
            // --- overlap next chunk's cp.async issue with LDSM latency ---
            if (ks == 0) {
                int nstg = stg + 2; if (nstg >= NSTG) nstg -= NSTG;
                if (ch + 2 < total) { LOAD_CHUNK(ch + 2, nstg); }
                CP_COMMIT();
            }
            // --- MMAs, streaming A tiles one ahead ---
#pragma unroll
            for (int i = 0; i < 4; i++) {
                if (i < 3) {
                    const int row = wm + (i + 1) * 16 + aRow;
                    const uint32_t ra = bb + row * 128;
                    LDSM4(ahn, ra + SWZC(row, colH + aCol0));
                    if (TERMS == 3) LDSM4(aln, ra + SWZC(row, colH + aCol0 + 64));
                }
#pragma unroll
                for (int j = 0; j < 4; j++) MMA(acc[i][j], ahc, bh[j]);
                if (TERMS == 3) {
#pragma unroll
                    for (int j = 0; j < 4; j++) MMA(acc[i][j], ahc, bl[j]);
#pragma unroll
                    for (int j = 0; j < 4; j++) MMA(acc[i][j], alc, bh[j]);
                }
#pragma unroll
                for (int r = 0; r < 4; r++) {
                    ahc[r] = ahn[r];
                    if (TERMS == 3) alc[r] = aln[r];
                }
            }
        }
        stg = stg + 1; if (stg >= NSTG) stg = 0;
    }
#undef LOAD_CHUNK

    // ---- epilogue (vectorized stores) ----
    const int cr = lane >> 2, cc = (lane & 3) * 2;
#pragma unroll
    for (int i = 0; i < 4; i++) {
        const int r0 = m0 + wm + i * 16 + cr;
#pragma unroll
        for (int j = 0; j < 4; j++) {
            const int col = n0 + wn + j * 8 + cc;
            const size_t o0 = (size_t)z * cBatch + (size_t)r0 * ldC + col;
            const size_t o1 = o0 + (size_t)8 * ldC;
            float v0 = acc[i][j][0] * alpha, v1 = acc[i][j][1] * alpha;
            float v2 = acc[i][j][2] * alpha, v3 = acc[i][j][3] * alpha;
            if (EPI == 0) {
                *(float2*)&Cf[o0] = make_float2(v0, v1);
                *(float2*)&Cf[o1] = make_float2(v2, v3);
            } else {
                float h0 = __half2float(__float2half_rn(v0));
                float h1 = __half2float(__float2half_rn(v1));
                float h2 = __half2float(__float2half_rn(v2));
                float h3 = __half2float(__float2half_rn(v3));
                *(__half2*)&Chi[o0] = __floats2half2_rn(v0, v1);
                *(__half2*)&Chi[o1] = __floats2half2_rn(v2, v3);
                *(__half2*)&Clo[o0] = __floats2half2_rn(v0 - h0, v1 - h1);
                *(__half2*)&Clo[o1] = __floats2half2_rn(v2 - h2, v3 - h3);
            }
        }
    }
}

// ---------------------------------------------------------------------------
// Split x -> xs (h/r, [B,N,D]) and xt (h only, [B,D,N])
// ---------------------------------------------------------------------------
__global__ __launch_bounds__(256) void split_x_kernel(const float* __restrict__ x) {
    __shared__ float t[32][33];
    const int b = blockIdx.z;
    const int d0 = blockIdx.x * 32, n0 = blockIdx.y * 32;
    const int tx = threadIdx.x & 31, ty = threadIdx.x >> 5;

    for (int i = ty; i < 32; i += 8)
        t[i][tx] = x[(size_t)b * N_ * D_ + (size_t)(n0 + i) * D_ + d0 + tx];
    __syncthreads();

    for (int i = ty; i < 32; i += 8) {
        float v = t[i][tx];
        __half h = __float2half_rn(v);
        size_t o = (size_t)b * N_ * D_ + (size_t)(n0 + i) * D_ + d0 + tx;
        g_xs_h[o] = h; g_xs_r[o] = __float2half_rn(v - __half2float(h));
    }
    for (int i = ty; i < 32; i += 8) {
        float v = t[tx][i];
        size_t o = (size_t)b * D_ * N_ + (size_t)(d0 + i) * N_ + n0 + tx;
        g_xt_h[o] = __float2half_rn(v);
    }
}

__global__ __launch_bounds__(256) void split_w_kernel(const float* __restrict__ W) {
    __shared__ float t[32][33];
    const int h = blockIdx.z;
    const int e0 = blockIdx.x * 32, d0 = blockIdx.y * 32;
    const int tx = threadIdx.x & 31, ty = threadIdx.x >> 5;

    for (int i = ty; i < 32; i += 8)
        t[i][tx] = W[(size_t)h * D_ * D_ + (size_t)(d0 + i) * D_ + e0 + tx];
    __syncthreads();

    for (int i = ty; i < 32; i += 8) {
        float v = t[tx][i];   // W[d0+tx][e0+i]
        __half hh = __float2half_rn(v);
        size_t o = (size_t)h * D_ * D_ + (size_t)(e0 + i) * D_ + d0 + tx;
        g_Wt_h[o] = hh; g_Wt_r[o] = __float2half_rn(v - __half2float(hh));
    }
}

// ---------------------------------------------------------------------------
// Softmax over rows of g_S; writes fp16 P (hi only)
// ---------------------------------------------------------------------------
__global__ __launch_bounds__(256) void softmax_split_kernel() {
    const size_t row = blockIdx.x;
    const float* p = g_S + row * N_;
    const int tid = threadIdx.x;
    __shared__ float red[8];

    float4 v = *(const float4*)&p[tid * 4];
    float m = fmaxf(fmaxf(v.x, v.y), fmaxf(v.z, v.w));
#pragma unroll
    for (int o = 16; o; o >>= 1) m = fmaxf(m, __shfl_xor_sync(0xFFFFFFFFu, m, o));
    if ((tid & 31) == 0) red[tid >> 5] = m;
    __syncthreads();
    float bm = red[0];
#pragma unroll
    for (int i = 1; i < 8; i++) bm = fmaxf(bm, red[i]);
    __syncthreads();

    v.x = __expf(v.x - bm); v.y = __expf(v.y - bm);
    v.z = __expf(v.z - bm); v.w = __expf(v.w - bm);
    float s = v.x + v.y + v.z + v.w;
#pragma unroll
    for (int o = 16; o; o >>= 1) s += __shfl_xor_sync(0xFFFFFFFFu, s, o);
    if ((tid & 31) == 0) red[tid >> 5] = s;
    __syncthreads();
    float bs = 0.f;
#pragma unroll
    for (int i = 0; i < 8; i++) bs += red[i];
    float inv = 1.0f / bs;

    __half2* dst = (__half2*)&g_P_h[row * N_ + tid * 4];
    dst[0] = __floats2half2_rn(v.x * inv, v.y * inv);
    dst[1] = __floats2half2_rn(v.z * inv, v.w * inv);
}

// ---------------------------------------------------------------------------
extern "C" void kernel_launch(void* const* d_in, const int* in_sizes, int n_in,
                              void* d_out, int out_size) {
    const float* x = (const float*)d_in[0];   // [8,1024,512]
    const float* W = (const float*)d_in[1];   // [4,512,512]
    float* out = (float*)d_out;               // [8,1024,512]

    cudaFuncSetAttribute(gemm_mma<0, 3>, cudaFuncAttributeMaxDynamicSharedMemorySize, GSMEM);
    cudaFuncSetAttribute(gemm_mma<1, 3>, cudaFuncAttributeMaxDynamicSharedMemorySize, GSMEM);
    cudaFuncSetAttribute(gemm_mma<0, 1>, cudaFuncAttributeMaxDynamicSharedMemorySize, GSMEM);

    __half *xs_h, *xs_r, *xt_h, *Wt_h, *Wt_r, *Y_h, *Y_r, *P_h;
    float* Sf;
    cudaGetSymbolAddress((void**)&xs_h, g_xs_h);
    cudaGetSymbolAddress((void**)&xs_r, g_xs_r);
    cudaGetSymbolAddress((void**)&xt_h, g_xt_h);
    cudaGetSymbolAddress((void**)&Wt_h, g_Wt_h);
    cudaGetSymbolAddress((void**)&Wt_r, g_Wt_r);
    cudaGetSymbolAddress((void**)&Y_h, g_Y_h);
    cudaGetSymbolAddress((void**)&Y_r, g_Y_r);
    cudaGetSymbolAddress((void**)&P_h, g_P_h);
    cudaGetSymbolAddress((void**)&Sf, g_S);

    const float SCALE = 0.04419417382415922f;   // 512^-0.5

    split_x_kernel<<<dim3(D_ / 32, N_ / 32, B_), 256>>>(x);
    split_w_kernel<<<dim3(D_ / 32, D_ / 32, H_), 256>>>(W);

    // K1: Y[b,h] = xs[b] @ Wt[h]^T  (3-term) -> fp16 h/r Y
    gemm_mma<1, 3><<<dim3(D_ / 128, N_ / 128, B_ * H_), 256, GSMEM>>>(
        xs_h, xs_r, D_, (size_t)N_ * D_, 4, 8, 0, 1,
        Wt_h, Wt_r, D_, (size_t)D_ * D_, 1, 4,
        D_,
        nullptr, Y_h, Y_r, D_, (size_t)N_ * D_, 1.0f);

    // K2: S[b,h] = scale * Y[b,h] @ xs[b]^T  (3-term) -> fp32
    gemm_mma<0, 3><<<dim3(N_ / 128, N_ / 128, B_ * H_), 256, GSMEM>>>(
        Y_h, Y_r, D_, (size_t)N_ * D_, 1, 32, 0, 1,
        xs_h, xs_r, D_, (size_t)N_ * D_, 4, 8,
        D_,
        Sf, nullptr, nullptr, N_, (size_t)N_ * N_, SCALE);

    softmax_split_kernel<<<B_ * H_ * N_, 256>>>();

    // K4: out[b] = 0.25 * sum_h P_h[b,h] @ xt_h[b]^T  (1-term fp16,
    //     4 head-segments accumulated in registers, direct out write)
    gemm_mma<0, 1><<<dim3(D_ / 128, N_ / 128, B_), 256, GSMEM>>>(
        P_h, nullptr, N_, (size_t)H_ * N_ * N_, 1, 8, (size_t)N_ * N_, H_,
        xt_h, nullptr, N_, (size_t)D_ * N_, 1, 8,
        N_,
        out, nullptr, nullptr, D_, (size_t)N_ * D_, 0.25f);
}